// round 5
// baseline (speedup 1.0000x reference)
#include <cuda_runtime.h>
#include <math.h>

#define BB 4
#define NN 20480
#define KK 16
#define BN (BB*NN)   // 81920 points

// ---------------- scratch (__device__ globals; no allocation allowed) ----------
__device__ float g_feat0[BN*16];
__device__ float g_feat1[BN*16];
__device__ float g_lrep[(size_t)BN*256];   // [p][k][c] 83.9MB
__device__ float g_gdis[BN*16];            // [p][k]
__device__ float g_lgr[BN];                // [p]

// ---------------- Kernel A: feat0 = relu(g*(m1_W @ feature)+b) ------------------
__global__ void __launch_bounds__(256) kA(const float* __restrict__ feature,
                                          const float* __restrict__ W,
                                          const float* __restrict__ g,
                                          const float* __restrict__ bia)
{
    __shared__ float sW[256], sg[16], sb[16];
    int tid = threadIdx.x;
    sW[tid] = W[tid];
    if (tid < 16) { sg[tid] = g[tid]; sb[tid] = bia[tid]; }
    __syncthreads();
    int p = blockIdx.x * 256 + tid;
    if (p >= BN) return;
    int b = p / NN, n = p - b * NN;
    const float* f = feature + (size_t)b * 16 * NN + n;
    float x[16];
#pragma unroll
    for (int c = 0; c < 16; c++) x[c] = f[(size_t)c * NN];
#pragma unroll
    for (int o = 0; o < 16; o++) {
        float a = 0.f;
#pragma unroll
        for (int c = 0; c < 16; c++) a = fmaf(sW[o * 16 + c], x[c], a);
        g_feat0[(size_t)p * 16 + o] = fmaxf(fmaf(a, sg[o], sb[o]), 0.f);
    }
}

// -------- attention pool for one lane (= one output channel c of 32) ------------
// cat layout: [34 rows][16 k]; fcT: transposed weights [34][33-padded]
__device__ __forceinline__ float pool_lane(const float* __restrict__ cat,
                                           const float* __restrict__ fcT, int c)
{
    float acc[16];
#pragma unroll
    for (int t = 0; t < 16; t++) acc[t] = 0.f;
#pragma unroll
    for (int i = 0; i < 34; i++) {
        float w = fcT[i * 33 + c];
        const float4* row = (const float4*)(cat + i * 16);
        float4 v0 = row[0], v1 = row[1], v2 = row[2], v3 = row[3];
        acc[0]  = fmaf(w, v0.x, acc[0]);  acc[1]  = fmaf(w, v0.y, acc[1]);
        acc[2]  = fmaf(w, v0.z, acc[2]);  acc[3]  = fmaf(w, v0.w, acc[3]);
        acc[4]  = fmaf(w, v1.x, acc[4]);  acc[5]  = fmaf(w, v1.y, acc[5]);
        acc[6]  = fmaf(w, v1.z, acc[6]);  acc[7]  = fmaf(w, v1.w, acc[7]);
        acc[8]  = fmaf(w, v2.x, acc[8]);  acc[9]  = fmaf(w, v2.y, acc[9]);
        acc[10] = fmaf(w, v2.z, acc[10]); acc[11] = fmaf(w, v2.w, acc[11]);
        acc[12] = fmaf(w, v3.x, acc[12]); acc[13] = fmaf(w, v3.y, acc[13]);
        acc[14] = fmaf(w, v3.z, acc[14]); acc[15] = fmaf(w, v3.w, acc[15]);
    }
    float m = acc[0];
#pragma unroll
    for (int t = 1; t < 16; t++) m = fmaxf(m, acc[t]);
    float s = 0.f;
#pragma unroll
    for (int t = 0; t < 16; t++) { acc[t] = __expf(acc[t] - m); s += acc[t]; }
    const float4* fr = (const float4*)(cat + (2 + c) * 16);
    float4 f0 = fr[0], f1 = fr[1], f2 = fr[2], f3 = fr[3];
    float fl = acc[0] * f0.x + acc[1] * f0.y + acc[2]  * f0.z + acc[3]  * f0.w
             + acc[4] * f1.x + acc[5] * f1.y + acc[6]  * f1.z + acc[7]  * f1.w
             + acc[8] * f2.x + acc[9] * f2.y + acc[10] * f2.z + acc[11] * f2.w
             + acc[12]* f3.x + acc[13]* f3.y + acc[14] * f3.z + acc[15] * f3.w;
    return fl / s;
}

// ---------------- Kernel B: geometry + lrep + pool1 -> feat1 --------------------
#define WB 8
__global__ void __launch_bounds__(256) kB(
    const float* __restrict__ xyz, const int* __restrict__ nidx,
    const float* __restrict__ lm1W, const float* __restrict__ lm1g, const float* __restrict__ lm1b,
    const float* __restrict__ fcW,
    const float* __restrict__ pmW, const float* __restrict__ pmg, const float* __restrict__ pmb)
{
    __shared__ float sLW[144], sLg[16], sLb[16];
    __shared__ float sFc[34 * 33];
    __shared__ float sPm[32 * 17];
    __shared__ float sPg[16], sPb[16];
    __shared__ __align__(16) float sCat[WB][544];
    __shared__ __align__(16) float sFlc[WB][32];

    int tid = threadIdx.x;
    for (int t = tid; t < 144; t += 256) sLW[t] = lm1W[t];
    if (tid < 16) { sLg[tid] = lm1g[tid]; sLb[tid] = lm1b[tid];
                    sPg[tid] = pmg[tid];  sPb[tid] = pmb[tid]; }
    for (int t = tid; t < 1088; t += 256) { int o = t / 34, i = t - o * 34; sFc[i * 33 + o] = fcW[t]; }
    for (int t = tid; t < 512;  t += 256) { int o = t >> 5, c = t & 31;     sPm[c * 17 + o] = pmW[t]; }
    __syncthreads();

    int warp = tid >> 5, lane = tid & 31;
    int k = lane & 15, h = lane >> 4, cbase = h * 8;
    float* cat = sCat[warp];
    float* flc = sFlc[warp];
    int nwarps = gridDim.x * WB;
    for (int p = blockIdx.x * WB + warp; p < BN; p += nwarps) {
        int b = p / NN;
        float Px = xyz[(size_t)p * 3 + 0], Py = xyz[(size_t)p * 3 + 1], Pz = xyz[(size_t)p * 3 + 2];
        int idx = nidx[(size_t)p * 16 + k];
        int nbp = b * NN + idx;
        float Qx = xyz[(size_t)nbp * 3 + 0], Qy = xyz[(size_t)nbp * 3 + 1], Qz = xyz[(size_t)nbp * 3 + 2];
        float rx = Px - Qx, ry = Py - Qy, rz = Pz - Qz;
        float rxy2 = rx * rx + ry * ry;
        float rd = sqrtf(rxy2 + rz * rz);
        float ral = atan2f(ry, rx);
        float rbe = atan2f(rz, sqrtf(rxy2));
        float gd = __expf(-rd);
        // 16-lane reductions (halves hold duplicate k-data; offsets <=8 stay in-half)
        float maxd = rd, sx = Qx, sy = Qy, sz = Qz;
#pragma unroll
        for (int off = 8; off; off >>= 1) {
            maxd = fmaxf(maxd, __shfl_xor_sync(0xffffffffu, maxd, off));
            sx += __shfl_xor_sync(0xffffffffu, sx, off);
            sy += __shfl_xor_sync(0xffffffffu, sy, off);
            sz += __shfl_xor_sync(0xffffffffu, sz, off);
        }
        float dvx = Px - sx * (1.f / 16.f), dvy = Py - sy * (1.f / 16.f), dvz = Pz - sz * (1.f / 16.f);
        float dal = atan2f(dvy, dvx);
        float dbe = atan2f(dvz, sqrtf(dvx * dvx + dvy * dvy));
        float rep[9] = { ral - dal, rbe - dbe, rd, Px, Py, Pz, Qx, Qy, Qz };
        float lrv[8];
#pragma unroll
        for (int j = 0; j < 8; j++) {
            int c = cbase + j;
            float a = 0.f;
#pragma unroll
            for (int i = 0; i < 9; i++) a = fmaf(sLW[c * 9 + i], rep[i], a);
            float v = fmaxf(fmaf(a, sLg[c], sLb[c]), 0.f);
            lrv[j] = v;
            cat[(18 + c) * 16 + k] = v;
        }
        {
            float4* dst = (float4*)(g_lrep + (size_t)p * 256 + k * 16 + cbase);
            dst[0] = make_float4(lrv[0], lrv[1], lrv[2], lrv[3]);
            dst[1] = make_float4(lrv[4], lrv[5], lrv[6], lrv[7]);
        }
        if (h == 0) { cat[k] = gd; g_gdis[(size_t)p * 16 + k] = gd; }
        if (lane == 0) {
            float gn2 = Px * Px + Py * Py + Pz * Pz;
            g_lgr[p] = (maxd * maxd * maxd) / (gn2 * sqrtf(gn2));
        }
        // feat0 gather + f_dis
        const float4* fq = (const float4*)(g_feat0 + (size_t)nbp * 16 + cbase);
        float4 a0 = fq[0], a1 = fq[1];
        const float4* fp4 = (const float4*)(g_feat0 + (size_t)p * 16 + cbase);
        float4 c0 = fp4[0], c1 = fp4[1];
        float pa = fabsf(a0.x - c0.x) + fabsf(a0.y - c0.y) + fabsf(a0.z - c0.z) + fabsf(a0.w - c0.w)
                 + fabsf(a1.x - c1.x) + fabsf(a1.y - c1.y) + fabsf(a1.z - c1.z) + fabsf(a1.w - c1.w);
        pa += __shfl_xor_sync(0xffffffffu, pa, 16);
        if (h == 0) cat[16 + k] = __expf(-pa * (1.f / 16.f)) * 2.0f;  // f_dis * LAMDA
        cat[(2 + cbase + 0) * 16 + k] = a0.x; cat[(2 + cbase + 1) * 16 + k] = a0.y;
        cat[(2 + cbase + 2) * 16 + k] = a0.z; cat[(2 + cbase + 3) * 16 + k] = a0.w;
        cat[(2 + cbase + 4) * 16 + k] = a1.x; cat[(2 + cbase + 5) * 16 + k] = a1.y;
        cat[(2 + cbase + 6) * 16 + k] = a1.z; cat[(2 + cbase + 7) * 16 + k] = a1.w;
        __syncwarp();
        float fl = pool_lane(cat, sFc, lane);
        flc[lane] = fl;
        __syncwarp();
        if (lane < 16) {
            float a = 0.f;
#pragma unroll
            for (int c = 0; c < 32; c++) a = fmaf(sPm[c * 17 + lane], flc[c], a);
            g_feat1[(size_t)p * 16 + lane] = fmaxf(fmaf(a, sPg[lane], sPb[lane]), 0.f);
        }
        __syncwarp();
    }
}

// ---------------- Kernel C: lrep2 + pool2 + p2m + m2/sc/m3 + m4 -----------------
#define WC 4
// shared layout (float offsets)
#define O_LM2W 0
#define O_LM2G 256
#define O_LM2B 272
#define O_FC2  288      /* 34*33 = 1122 */
#define O_P2M  1410     /* 32*33 = 1056 */
#define O_P2G  2466
#define O_P2B  2498
#define O_M2   2530     /* 32*65 = 2080 */
#define O_M2G  4610
#define O_M2B  4674
#define O_SC   4738     /* 16*65 = 1040 */
#define O_SCG  5778
#define O_SCB  5842
#define O_M3   5906     /* 4*65 = 260 */
#define O_M3G  6166
#define O_M3B  6230
#define O_M4   6294     /* 128*65 = 8320 */
#define O_M4G  14614
#define O_M4B  14678
#define O_WARP 14744
#define WSTRIDE 752     /* cat 544 + flc 32 + tmp 32 + comb 128 + pf 16 */
#define SMEM_C_FLOATS (O_WARP + WC * WSTRIDE)   /* 17752 floats = 71008 B */

__global__ void __launch_bounds__(128) kC(
    const float* __restrict__ feature, const float* __restrict__ xyz, const int* __restrict__ nidx,
    const float* __restrict__ lm2W, const float* __restrict__ lm2g, const float* __restrict__ lm2b,
    const float* __restrict__ fc2W,
    const float* __restrict__ p2mW, const float* __restrict__ p2mg, const float* __restrict__ p2mb,
    const float* __restrict__ m2W, const float* __restrict__ m2g, const float* __restrict__ m2b,
    const float* __restrict__ scW, const float* __restrict__ scg, const float* __restrict__ scb,
    const float* __restrict__ m3W, const float* __restrict__ m3g, const float* __restrict__ m3b,
    const float* __restrict__ m4W, const float* __restrict__ m4g, const float* __restrict__ m4b,
    float* __restrict__ out)
{
    extern __shared__ float sh[];
    int tid = threadIdx.x;
    for (int t = tid; t < 256;  t += 128) sh[O_LM2W + t] = lm2W[t];
    for (int t = tid; t < 16;   t += 128) { sh[O_LM2G + t] = lm2g[t]; sh[O_LM2B + t] = lm2b[t]; }
    for (int t = tid; t < 1088; t += 128) { int o = t / 34, i = t - o * 34; sh[O_FC2 + i * 33 + o] = fc2W[t]; }
    for (int t = tid; t < 1024; t += 128) { int o = t >> 5, c = t & 31; sh[O_P2M + c * 33 + o] = p2mW[t]; }
    for (int t = tid; t < 32;   t += 128) { sh[O_P2G + t] = p2mg[t]; sh[O_P2B + t] = p2mb[t]; }
    for (int t = tid; t < 2048; t += 128) { int o = t >> 5, c = t & 31; sh[O_M2 + c * 65 + o] = m2W[t]; }
    for (int t = tid; t < 64;   t += 128) {
        sh[O_M2G + t] = m2g[t]; sh[O_M2B + t] = m2b[t];
        sh[O_SCG + t] = scg[t]; sh[O_SCB + t] = scb[t];
        sh[O_M3G + t] = m3g[t]; sh[O_M3B + t] = m3b[t];
        sh[O_M4G + t] = m4g[t]; sh[O_M4B + t] = m4b[t];
    }
    for (int t = tid; t < 1024; t += 128) { int o = t >> 4, c = t & 15; sh[O_SC + c * 65 + o] = scW[t]; }
    for (int t = tid; t < 256;  t += 128) { int o = t >> 2, c = t & 3;  sh[O_M3 + c * 65 + o] = m3W[t]; }
    for (int t = tid; t < 8192; t += 128) { int o = t >> 7, i = t & 127; sh[O_M4 + i * 65 + o] = m4W[t]; }
    __syncthreads();

    int warp = tid >> 5, lane = tid & 31, k = lane & 15, h = lane >> 4, cbase = h * 8;
    float* wsh  = sh + O_WARP + warp * WSTRIDE;
    float* cat  = wsh;
    float* flc  = wsh + 544;
    float* tmp  = wsh + 576;
    float* comb = wsh + 608;
    float* pf   = wsh + 736;
    int nwarps = gridDim.x * WC;
    for (int p = blockIdx.x * WC + warp; p < BN; p += nwarps) {
        int b = p / NN, n = p - b * NN;
        const float4* lq = (const float4*)(g_lrep + (size_t)p * 256 + k * 16);
        float4 L0 = lq[0], L1 = lq[1], L2 = lq[2], L3 = lq[3];
        float lr[16] = { L0.x, L0.y, L0.z, L0.w, L1.x, L1.y, L1.z, L1.w,
                         L2.x, L2.y, L2.z, L2.w, L3.x, L3.y, L3.z, L3.w };
#pragma unroll
        for (int j = 0; j < 8; j++) {
            int c = cbase + j;
            float a = 0.f;
#pragma unroll
            for (int i = 0; i < 16; i++) a = fmaf(sh[O_LM2W + c * 16 + i], lr[i], a);
            cat[(18 + c) * 16 + k] = fmaxf(fmaf(a, sh[O_LM2G + c], sh[O_LM2B + c]), 0.f);
        }
        if (h == 0) cat[k] = g_gdis[(size_t)p * 16 + k];
        int idx = nidx[(size_t)p * 16 + k];
        int nbp = b * NN + idx;
        const float4* fq = (const float4*)(g_feat1 + (size_t)nbp * 16 + cbase);
        float4 a0 = fq[0], a1 = fq[1];
        const float4* fp4 = (const float4*)(g_feat1 + (size_t)p * 16 + cbase);
        float4 c0 = fp4[0], c1 = fp4[1];
        float pa = fabsf(a0.x - c0.x) + fabsf(a0.y - c0.y) + fabsf(a0.z - c0.z) + fabsf(a0.w - c0.w)
                 + fabsf(a1.x - c1.x) + fabsf(a1.y - c1.y) + fabsf(a1.z - c1.z) + fabsf(a1.w - c1.w);
        pa += __shfl_xor_sync(0xffffffffu, pa, 16);
        if (h == 0) cat[16 + k] = __expf(-pa * (1.f / 16.f)) * 2.0f;
        cat[(2 + cbase + 0) * 16 + k] = a0.x; cat[(2 + cbase + 1) * 16 + k] = a0.y;
        cat[(2 + cbase + 2) * 16 + k] = a0.z; cat[(2 + cbase + 3) * 16 + k] = a0.w;
        cat[(2 + cbase + 4) * 16 + k] = a1.x; cat[(2 + cbase + 5) * 16 + k] = a1.y;
        cat[(2 + cbase + 6) * 16 + k] = a1.z; cat[(2 + cbase + 7) * 16 + k] = a1.w;
        if (lane < 16) pf[lane] = feature[(size_t)b * 16 * NN + (size_t)lane * NN + n];
        __syncwarp();
        float fl = pool_lane(cat, sh + O_FC2, lane);
        flc[lane] = fl;
        __syncwarp();
        {   // p2m (relu)
            float a = 0.f;
#pragma unroll
            for (int c = 0; c < 32; c++) a = fmaf(sh[O_P2M + c * 33 + lane], flc[c], a);
            tmp[lane] = fmaxf(fmaf(a, sh[O_P2G + lane], sh[O_P2B + lane]), 0.f);
        }
        __syncwarp();
        // m2 (no relu) + sc (no relu) + m3 (no relu)
        float A1 = 0.f, A2 = 0.f;
#pragma unroll
        for (int c = 0; c < 32; c++) {
            float f = tmp[c];
            A1 = fmaf(sh[O_M2 + c * 65 + lane], f, A1);
            A2 = fmaf(sh[O_M2 + c * 65 + 32 + lane], f, A2);
        }
        A1 = fmaf(A1, sh[O_M2G + lane], sh[O_M2B + lane]);
        A2 = fmaf(A2, sh[O_M2G + 32 + lane], sh[O_M2B + 32 + lane]);
        float S1 = 0.f, S2 = 0.f;
#pragma unroll
        for (int c = 0; c < 16; c++) {
            float f = pf[c];
            S1 = fmaf(sh[O_SC + c * 65 + lane], f, S1);
            S2 = fmaf(sh[O_SC + c * 65 + 32 + lane], f, S2);
        }
        S1 = fmaf(S1, sh[O_SCG + lane], sh[O_SCB + lane]);
        S2 = fmaf(S2, sh[O_SCG + 32 + lane], sh[O_SCB + 32 + lane]);
        comb[lane]      = A1 + S1;
        comb[32 + lane] = A2 + S2;
        float Px = xyz[(size_t)p * 3], Py = xyz[(size_t)p * 3 + 1], Pz = xyz[(size_t)p * 3 + 2];
        float lgr = g_lgr[p];
        float G1 = sh[O_M3 + 0 * 65 + lane] * Px + sh[O_M3 + 1 * 65 + lane] * Py
                 + sh[O_M3 + 2 * 65 + lane] * Pz + sh[O_M3 + 3 * 65 + lane] * lgr;
        float G2 = sh[O_M3 + 0 * 65 + 32 + lane] * Px + sh[O_M3 + 1 * 65 + 32 + lane] * Py
                 + sh[O_M3 + 2 * 65 + 32 + lane] * Pz + sh[O_M3 + 3 * 65 + 32 + lane] * lgr;
        comb[64 + lane] = fmaf(G1, sh[O_M3G + lane], sh[O_M3B + lane]);
        comb[96 + lane] = fmaf(G2, sh[O_M3G + 32 + lane], sh[O_M3B + 32 + lane]);
        __syncwarp();
        // m4 (relu)
        float B1 = 0.f, B2 = 0.f;
#pragma unroll
        for (int i = 0; i < 128; i += 4) {
            float4 cv = *(const float4*)(comb + i);
            B1 = fmaf(sh[O_M4 + (i + 0) * 65 + lane], cv.x, B1);
            B1 = fmaf(sh[O_M4 + (i + 1) * 65 + lane], cv.y, B1);
            B1 = fmaf(sh[O_M4 + (i + 2) * 65 + lane], cv.z, B1);
            B1 = fmaf(sh[O_M4 + (i + 3) * 65 + lane], cv.w, B1);
            B2 = fmaf(sh[O_M4 + (i + 0) * 65 + 32 + lane], cv.x, B2);
            B2 = fmaf(sh[O_M4 + (i + 1) * 65 + 32 + lane], cv.y, B2);
            B2 = fmaf(sh[O_M4 + (i + 2) * 65 + 32 + lane], cv.z, B2);
            B2 = fmaf(sh[O_M4 + (i + 3) * 65 + 32 + lane], cv.w, B2);
        }
        out[((size_t)b * 64 + lane) * NN + n]      = fmaxf(fmaf(B1, sh[O_M4G + lane], sh[O_M4B + lane]), 0.f);
        out[((size_t)b * 64 + 32 + lane) * NN + n] = fmaxf(fmaf(B2, sh[O_M4G + 32 + lane], sh[O_M4B + 32 + lane]), 0.f);
        __syncwarp();
    }
}

// -------------------------------- launcher --------------------------------------
extern "C" void kernel_launch(void* const* d_in, const int* in_sizes, int n_in,
                              void* d_out, int out_size)
{
    const float* feature = (const float*)d_in[0];
    const float* xyz     = (const float*)d_in[1];
    const float* m1W  = (const float*)d_in[2];
    const float* m1g  = (const float*)d_in[3];
    const float* m1b  = (const float*)d_in[4];
    const float* lm1W = (const float*)d_in[5];
    const float* lm1g = (const float*)d_in[6];
    const float* lm1b = (const float*)d_in[7];
    const float* lm2W = (const float*)d_in[8];
    const float* lm2g = (const float*)d_in[9];
    const float* lm2b = (const float*)d_in[10];
    const float* p1fcW= (const float*)d_in[11];
    const float* p1mW = (const float*)d_in[12];
    const float* p1mg = (const float*)d_in[13];
    const float* p1mb = (const float*)d_in[14];
    const float* p2fcW= (const float*)d_in[15];
    const float* p2mW = (const float*)d_in[16];
    const float* p2mg = (const float*)d_in[17];
    const float* p2mb = (const float*)d_in[18];
    const float* m2W  = (const float*)d_in[19];
    const float* m2g  = (const float*)d_in[20];
    const float* m2b  = (const float*)d_in[21];
    const float* scW  = (const float*)d_in[22];
    const float* scg  = (const float*)d_in[23];
    const float* scb  = (const float*)d_in[24];
    const float* m3W  = (const float*)d_in[25];
    const float* m3g  = (const float*)d_in[26];
    const float* m3b  = (const float*)d_in[27];
    const float* m4W  = (const float*)d_in[28];
    const float* m4g  = (const float*)d_in[29];
    const float* m4b  = (const float*)d_in[30];
    const int*   nidx = (const int*)d_in[31];
    float* out = (float*)d_out;

    static bool attr_done = false;
    if (!attr_done) {
        cudaFuncSetAttribute(kC, cudaFuncAttributeMaxDynamicSharedMemorySize,
                             SMEM_C_FLOATS * (int)sizeof(float));
        attr_done = true;
    }

    kA<<<(BN + 255) / 256, 256>>>(feature, m1W, m1g, m1b);
    kB<<<1184, 256>>>(xyz, nidx, lm1W, lm1g, lm1b, p1fcW, p1mW, p1mg, p1mb);
    kC<<<444, 128, SMEM_C_FLOATS * sizeof(float)>>>(
        feature, xyz, nidx,
        lm2W, lm2g, lm2b, p2fcW, p2mW, p2mg, p2mb,
        m2W, m2g, m2b, scW, scg, scb, m3W, m3g, m3b, m4W, m4g, m4b, out);
}

// round 9
// speedup vs baseline: 1.0470x; 1.0470x over previous
#include <cuda_runtime.h>
#include <math.h>

#define BB 4
#define NN 20480
#define KK 16
#define BN (BB*NN)   // 81920 points

// ---------------- scratch (__device__ globals; no allocation allowed) ----------
__device__ float g_feat0[BN*16];
__device__ float g_feat1[BN*16];
__device__ float g_lrep[(size_t)BN*256];   // [p][k][c] 83.9MB
__device__ float g_gdis[BN*16];            // [p][k]
__device__ float g_lgr[BN];                // [p]

// ---------------- packed f32x2 helpers ------------------------------------------
__device__ __forceinline__ unsigned long long ffma2(unsigned long long a,
                                                    unsigned long long b,
                                                    unsigned long long c)
{
    unsigned long long d;
    asm("fma.rn.f32x2 %0, %1, %2, %3;" : "=l"(d) : "l"(a), "l"(b), "l"(c));
    return d;
}
__device__ __forceinline__ unsigned long long pack2(float x)
{
    unsigned long long d;
    asm("mov.b64 %0, {%1, %1};" : "=l"(d) : "f"(x));
    return d;
}
__device__ __forceinline__ float2 unpack2(unsigned long long v)
{
    float lo, hi;
    asm("mov.b64 {%0, %1}, %2;" : "=f"(lo), "=f"(hi) : "l"(v));
    return make_float2(lo, hi);
}

// ---------------- Kernel A: feat0 = relu(g*(m1_W @ feature)+b) ------------------
__global__ void __launch_bounds__(256) kA(const float* __restrict__ feature,
                                          const float* __restrict__ W,
                                          const float* __restrict__ g,
                                          const float* __restrict__ bia)
{
    __shared__ float sW[256], sg[16], sb[16];
    int tid = threadIdx.x;
    sW[tid] = W[tid];
    if (tid < 16) { sg[tid] = g[tid]; sb[tid] = bia[tid]; }
    __syncthreads();
    int p = blockIdx.x * 256 + tid;
    if (p >= BN) return;
    int b = p / NN, n = p - b * NN;
    const float* f = feature + (size_t)b * 16 * NN + n;
    float x[16];
#pragma unroll
    for (int c = 0; c < 16; c++) x[c] = f[(size_t)c * NN];
#pragma unroll
    for (int o = 0; o < 16; o++) {
        float a = 0.f;
#pragma unroll
        for (int c = 0; c < 16; c++) a = fmaf(sW[o * 16 + c], x[c], a);
        g_feat0[(size_t)p * 16 + o] = fmaxf(fmaf(a, sg[o], sb[o]), 0.f);
    }
}

// -------- attention pool for one lane (= one output channel c of 32) ------------
// cat layout: [34 rows][16 k] (16B-aligned); fcT: transposed weights [34][33-pad]
// K-dimension packed in f32x2: acc[t] holds k=2t,2t+1.
__device__ __forceinline__ float pool_lane(const float* __restrict__ cat,
                                           const float* __restrict__ fcT, int c)
{
    unsigned long long acc[8];
#pragma unroll
    for (int t = 0; t < 8; t++) acc[t] = 0ull;
#pragma unroll
    for (int i = 0; i < 34; i++) {
        unsigned long long w2 = pack2(fcT[i * 33 + c]);
        const ulonglong2* row = (const ulonglong2*)(cat + i * 16);
        ulonglong2 r0 = row[0], r1 = row[1], r2 = row[2], r3 = row[3];
        acc[0] = ffma2(w2, r0.x, acc[0]); acc[1] = ffma2(w2, r0.y, acc[1]);
        acc[2] = ffma2(w2, r1.x, acc[2]); acc[3] = ffma2(w2, r1.y, acc[3]);
        acc[4] = ffma2(w2, r2.x, acc[4]); acc[5] = ffma2(w2, r2.y, acc[5]);
        acc[6] = ffma2(w2, r3.x, acc[6]); acc[7] = ffma2(w2, r3.y, acc[7]);
    }
    float a[16];
#pragma unroll
    for (int t = 0; t < 8; t++) { float2 u = unpack2(acc[t]); a[2*t] = u.x; a[2*t+1] = u.y; }
    float m = a[0];
#pragma unroll
    for (int t = 1; t < 16; t++) m = fmaxf(m, a[t]);
    float s = 0.f;
#pragma unroll
    for (int t = 0; t < 16; t++) { a[t] = __expf(a[t] - m); s += a[t]; }
    const float4* fr = (const float4*)(cat + (2 + c) * 16);
    float4 f0 = fr[0], f1 = fr[1], f2 = fr[2], f3 = fr[3];
    float fl = a[0] * f0.x + a[1] * f0.y + a[2]  * f0.z + a[3]  * f0.w
             + a[4] * f1.x + a[5] * f1.y + a[6]  * f1.z + a[7]  * f1.w
             + a[8] * f2.x + a[9] * f2.y + a[10] * f2.z + a[11] * f2.w
             + a[12]* f3.x + a[13]* f3.y + a[14] * f3.z + a[15] * f3.w;
    return fl / s;
}

// ---------------- Kernel B: geometry + lrep + pool1 -> feat1 --------------------
#define WB 8
__global__ void __launch_bounds__(256) kB(
    const float* __restrict__ xyz, const int* __restrict__ nidx,
    const float* __restrict__ lm1W, const float* __restrict__ lm1g, const float* __restrict__ lm1b,
    const float* __restrict__ fcW,
    const float* __restrict__ pmW, const float* __restrict__ pmg, const float* __restrict__ pmb)
{
    __shared__ float sLW[144], sLg[16], sLb[16];
    __shared__ float sFc[34 * 33];
    __shared__ float sPm[32 * 17];
    __shared__ float sPg[16], sPb[16];
    __shared__ __align__(16) float sCat[WB][544];
    __shared__ __align__(16) float sFlc[WB][32];

    int tid = threadIdx.x;
    for (int t = tid; t < 144; t += 256) sLW[t] = lm1W[t];
    if (tid < 16) { sLg[tid] = lm1g[tid]; sLb[tid] = lm1b[tid];
                    sPg[tid] = pmg[tid];  sPb[tid] = pmb[tid]; }
    for (int t = tid; t < 1088; t += 256) { int o = t / 34, i = t - o * 34; sFc[i * 33 + o] = fcW[t]; }
    for (int t = tid; t < 512;  t += 256) { int o = t >> 5, c = t & 31;     sPm[c * 17 + o] = pmW[t]; }
    __syncthreads();

    int warp = tid >> 5, lane = tid & 31;
    int k = lane & 15, h = lane >> 4, cbase = h * 8;
    float* cat = sCat[warp];
    float* flc = sFlc[warp];
    int nwarps = gridDim.x * WB;
    for (int p = blockIdx.x * WB + warp; p < BN; p += nwarps) {
        int b = p / NN;
        float Px = xyz[(size_t)p * 3 + 0], Py = xyz[(size_t)p * 3 + 1], Pz = xyz[(size_t)p * 3 + 2];
        int idx = nidx[(size_t)p * 16 + k];
        int nbp = b * NN + idx;
        float Qx = xyz[(size_t)nbp * 3 + 0], Qy = xyz[(size_t)nbp * 3 + 1], Qz = xyz[(size_t)nbp * 3 + 2];
        float rx = Px - Qx, ry = Py - Qy, rz = Pz - Qz;
        float rxy2 = rx * rx + ry * ry;
        float rd = sqrtf(rxy2 + rz * rz);
        float ral = atan2f(ry, rx);
        float rbe = atan2f(rz, sqrtf(rxy2));
        float gd = __expf(-rd);
        // 16-lane reductions (halves hold duplicate k-data; offsets <=8 stay in-half)
        float maxd = rd, sx = Qx, sy = Qy, sz = Qz;
#pragma unroll
        for (int off = 8; off; off >>= 1) {
            maxd = fmaxf(maxd, __shfl_xor_sync(0xffffffffu, maxd, off));
            sx += __shfl_xor_sync(0xffffffffu, sx, off);
            sy += __shfl_xor_sync(0xffffffffu, sy, off);
            sz += __shfl_xor_sync(0xffffffffu, sz, off);
        }
        float dvx = Px - sx * (1.f / 16.f), dvy = Py - sy * (1.f / 16.f), dvz = Pz - sz * (1.f / 16.f);
        float dal = atan2f(dvy, dvx);
        float dbe = atan2f(dvz, sqrtf(dvx * dvx + dvy * dvy));
        float rep[9] = { ral - dal, rbe - dbe, rd, Px, Py, Pz, Qx, Qy, Qz };
        float lrv[8];
#pragma unroll
        for (int j = 0; j < 8; j++) {
            int c = cbase + j;
            float a = 0.f;
#pragma unroll
            for (int i = 0; i < 9; i++) a = fmaf(sLW[c * 9 + i], rep[i], a);
            float v = fmaxf(fmaf(a, sLg[c], sLb[c]), 0.f);
            lrv[j] = v;
            cat[(18 + c) * 16 + k] = v;
        }
        {
            float4* dst = (float4*)(g_lrep + (size_t)p * 256 + k * 16 + cbase);
            dst[0] = make_float4(lrv[0], lrv[1], lrv[2], lrv[3]);
            dst[1] = make_float4(lrv[4], lrv[5], lrv[6], lrv[7]);
        }
        if (h == 0) { cat[k] = gd; g_gdis[(size_t)p * 16 + k] = gd; }
        if (lane == 0) {
            float gn2 = Px * Px + Py * Py + Pz * Pz;
            g_lgr[p] = (maxd * maxd * maxd) / (gn2 * sqrtf(gn2));
        }
        // feat0 gather + f_dis
        const float4* fq = (const float4*)(g_feat0 + (size_t)nbp * 16 + cbase);
        float4 a0 = fq[0], a1 = fq[1];
        const float4* fp4 = (const float4*)(g_feat0 + (size_t)p * 16 + cbase);
        float4 c0 = fp4[0], c1 = fp4[1];
        float pa = fabsf(a0.x - c0.x) + fabsf(a0.y - c0.y) + fabsf(a0.z - c0.z) + fabsf(a0.w - c0.w)
                 + fabsf(a1.x - c1.x) + fabsf(a1.y - c1.y) + fabsf(a1.z - c1.z) + fabsf(a1.w - c1.w);
        pa += __shfl_xor_sync(0xffffffffu, pa, 16);
        if (h == 0) cat[16 + k] = __expf(-pa * (1.f / 16.f)) * 2.0f;  // f_dis * LAMDA
        cat[(2 + cbase + 0) * 16 + k] = a0.x; cat[(2 + cbase + 1) * 16 + k] = a0.y;
        cat[(2 + cbase + 2) * 16 + k] = a0.z; cat[(2 + cbase + 3) * 16 + k] = a0.w;
        cat[(2 + cbase + 4) * 16 + k] = a1.x; cat[(2 + cbase + 5) * 16 + k] = a1.y;
        cat[(2 + cbase + 6) * 16 + k] = a1.z; cat[(2 + cbase + 7) * 16 + k] = a1.w;
        __syncwarp();
        float fl = pool_lane(cat, sFc, lane);
        flc[lane] = fl;
        __syncwarp();
        if (lane < 16) {
            float a = 0.f;
#pragma unroll
            for (int c = 0; c < 32; c++) a = fmaf(sPm[c * 17 + lane], flc[c], a);
            g_feat1[(size_t)p * 16 + lane] = fmaxf(fmaf(a, sPg[lane], sPb[lane]), 0.f);
        }
        __syncwarp();
    }
}

// ---------------- Kernel C: lrep2 + pool2 + p2m + m2/sc/m3 + m4 -----------------
#define WC 8
// shared layout (float offsets)
#define O_LM2W 0
#define O_LM2G 256
#define O_LM2B 272
#define O_FC2  288      /* 34*33 = 1122 */
#define O_P2M  1410     /* 32*33 = 1056 */
#define O_P2G  2466
#define O_P2B  2498
#define O_M2   2530     /* 32*65 = 2080 */
#define O_M2G  4610
#define O_M2B  4674
#define O_SC   4738     /* 16*65 = 1040 */
#define O_SCG  5778
#define O_SCB  5842
#define O_M3   5906     /* 4*65 = 260 */
#define O_M3G  6166
#define O_M3B  6230
#define O_M4A  6294     /* packed [i-pair][lane][2] for o=lane     : 4096 */
#define O_M4B  10390    /* packed [i-pair][lane][2] for o=lane+32  : 4096 */
#define O_M4G  14486
#define O_M4BI 14550
#define O_WARP 14616    /* multiple of 4 for float4/ulonglong2 alignment */
#define WSTRIDE 752     /* cat 544 + flc 32 + tmp 32 + comb 128 + pf 16 */
#define SMEM_C_FLOATS (O_WARP + WC * WSTRIDE)   /* 20632 floats = 82528 B */

__global__ void __launch_bounds__(256) kC(
    const float* __restrict__ feature, const float* __restrict__ xyz, const int* __restrict__ nidx,
    const float* __restrict__ lm2W, const float* __restrict__ lm2g, const float* __restrict__ lm2b,
    const float* __restrict__ fc2W,
    const float* __restrict__ p2mW, const float* __restrict__ p2mg, const float* __restrict__ p2mb,
    const float* __restrict__ m2W, const float* __restrict__ m2g, const float* __restrict__ m2b,
    const float* __restrict__ scW, const float* __restrict__ scg, const float* __restrict__ scb,
    const float* __restrict__ m3W, const float* __restrict__ m3g, const float* __restrict__ m3b,
    const float* __restrict__ m4W, const float* __restrict__ m4g, const float* __restrict__ m4b,
    float* __restrict__ out)
{
    extern __shared__ float sh[];
    int tid = threadIdx.x;
    for (int t = tid; t < 256;  t += 256) sh[O_LM2W + t] = lm2W[t];
    for (int t = tid; t < 16;   t += 256) { sh[O_LM2G + t] = lm2g[t]; sh[O_LM2B + t] = lm2b[t]; }
    for (int t = tid; t < 1088; t += 256) { int o = t / 34, i = t - o * 34; sh[O_FC2 + i * 33 + o] = fc2W[t]; }
    for (int t = tid; t < 1024; t += 256) { int o = t >> 5, c = t & 31; sh[O_P2M + c * 33 + o] = p2mW[t]; }
    for (int t = tid; t < 32;   t += 256) { sh[O_P2G + t] = p2mg[t]; sh[O_P2B + t] = p2mb[t]; }
    for (int t = tid; t < 2048; t += 256) { int o = t >> 5, c = t & 31; sh[O_M2 + c * 65 + o] = m2W[t]; }
    for (int t = tid; t < 64;   t += 256) {
        sh[O_M2G + t] = m2g[t]; sh[O_M2B + t] = m2b[t];
        sh[O_SCG + t] = scg[t]; sh[O_SCB + t] = scb[t];
        sh[O_M3G + t] = m3g[t]; sh[O_M3B + t] = m3b[t];
        sh[O_M4G + t] = m4g[t]; sh[O_M4BI + t] = m4b[t];
    }
    for (int t = tid; t < 1024; t += 256) { int o = t >> 4, c = t & 15; sh[O_SC + c * 65 + o] = scW[t]; }
    for (int t = tid; t < 256;  t += 256) { int o = t >> 2, c = t & 3;  sh[O_M3 + c * 65 + o] = m3W[t]; }
    // m4 packed staging: m4W is [o=64][i=128]; pair p=i/2, half=i&1
    for (int t = tid; t < 8192; t += 256) {
        int o = t >> 7, i = t & 127;
        int p = i >> 1, hf = i & 1;
        if (o < 32) sh[O_M4A + (p * 32 + o) * 2 + hf] = m4W[t];
        else        sh[O_M4B + (p * 32 + (o - 32)) * 2 + hf] = m4W[t];
    }
    __syncthreads();

    int warp = tid >> 5, lane = tid & 31, k = lane & 15, h = lane >> 4, cbase = h * 8;
    float* wsh  = sh + O_WARP + warp * WSTRIDE;
    float* cat  = wsh;
    float* flc  = wsh + 544;
    float* tmp  = wsh + 576;
    float* comb = wsh + 608;
    float* pf   = wsh + 736;
    int nwarps = gridDim.x * WC;
    for (int p = blockIdx.x * WC + warp; p < BN; p += nwarps) {
        int b = p / NN, n = p - b * NN;
        const float4* lq = (const float4*)(g_lrep + (size_t)p * 256 + k * 16);
        float4 L0 = lq[0], L1 = lq[1], L2 = lq[2], L3 = lq[3];
        float lr[16] = { L0.x, L0.y, L0.z, L0.w, L1.x, L1.y, L1.z, L1.w,
                         L2.x, L2.y, L2.z, L2.w, L3.x, L3.y, L3.z, L3.w };
#pragma unroll
        for (int j = 0; j < 8; j++) {
            int c = cbase + j;
            float a = 0.f;
#pragma unroll
            for (int i = 0; i < 16; i++) a = fmaf(sh[O_LM2W + c * 16 + i], lr[i], a);
            cat[(18 + c) * 16 + k] = fmaxf(fmaf(a, sh[O_LM2G + c], sh[O_LM2B + c]), 0.f);
        }
        if (h == 0) cat[k] = g_gdis[(size_t)p * 16 + k];
        int idx = nidx[(size_t)p * 16 + k];
        int nbp = b * NN + idx;
        const float4* fq = (const float4*)(g_feat1 + (size_t)nbp * 16 + cbase);
        float4 a0 = fq[0], a1 = fq[1];
        const float4* fp4 = (const float4*)(g_feat1 + (size_t)p * 16 + cbase);
        float4 c0 = fp4[0], c1 = fp4[1];
        float pa = fabsf(a0.x - c0.x) + fabsf(a0.y - c0.y) + fabsf(a0.z - c0.z) + fabsf(a0.w - c0.w)
                 + fabsf(a1.x - c1.x) + fabsf(a1.y - c1.y) + fabsf(a1.z - c1.z) + fabsf(a1.w - c1.w);
        pa += __shfl_xor_sync(0xffffffffu, pa, 16);
        if (h == 0) cat[16 + k] = __expf(-pa * (1.f / 16.f)) * 2.0f;
        cat[(2 + cbase + 0) * 16 + k] = a0.x; cat[(2 + cbase + 1) * 16 + k] = a0.y;
        cat[(2 + cbase + 2) * 16 + k] = a0.z; cat[(2 + cbase + 3) * 16 + k] = a0.w;
        cat[(2 + cbase + 4) * 16 + k] = a1.x; cat[(2 + cbase + 5) * 16 + k] = a1.y;
        cat[(2 + cbase + 6) * 16 + k] = a1.z; cat[(2 + cbase + 7) * 16 + k] = a1.w;
        if (lane < 16) pf[lane] = feature[(size_t)b * 16 * NN + (size_t)lane * NN + n];
        __syncwarp();
        float fl = pool_lane(cat, sh + O_FC2, lane);
        flc[lane] = fl;
        __syncwarp();
        {   // p2m (relu)
            float a = 0.f;
#pragma unroll
            for (int c = 0; c < 32; c++) a = fmaf(sh[O_P2M + c * 33 + lane], flc[c], a);
            tmp[lane] = fmaxf(fmaf(a, sh[O_P2G + lane], sh[O_P2B + lane]), 0.f);
        }
        __syncwarp();
        // m2 (no relu) + sc (no relu) + m3 (no relu)
        float A1 = 0.f, A2 = 0.f;
#pragma unroll
        for (int c = 0; c < 32; c++) {
            float f = tmp[c];
            A1 = fmaf(sh[O_M2 + c * 65 + lane], f, A1);
            A2 = fmaf(sh[O_M2 + c * 65 + 32 + lane], f, A2);
        }
        A1 = fmaf(A1, sh[O_M2G + lane], sh[O_M2B + lane]);
        A2 = fmaf(A2, sh[O_M2G + 32 + lane], sh[O_M2B + 32 + lane]);
        float S1 = 0.f, S2 = 0.f;
#pragma unroll
        for (int c = 0; c < 16; c++) {
            float f = pf[c];
            S1 = fmaf(sh[O_SC + c * 65 + lane], f, S1);
            S2 = fmaf(sh[O_SC + c * 65 + 32 + lane], f, S2);
        }
        S1 = fmaf(S1, sh[O_SCG + lane], sh[O_SCB + lane]);
        S2 = fmaf(S2, sh[O_SCG + 32 + lane], sh[O_SCB + 32 + lane]);
        comb[lane]      = A1 + S1;
        comb[32 + lane] = A2 + S2;
        float Px = xyz[(size_t)p * 3], Py = xyz[(size_t)p * 3 + 1], Pz = xyz[(size_t)p * 3 + 2];
        float lgr = g_lgr[p];
        float G1 = sh[O_M3 + 0 * 65 + lane] * Px + sh[O_M3 + 1 * 65 + lane] * Py
                 + sh[O_M3 + 2 * 65 + lane] * Pz + sh[O_M3 + 3 * 65 + lane] * lgr;
        float G2 = sh[O_M3 + 0 * 65 + 32 + lane] * Px + sh[O_M3 + 1 * 65 + 32 + lane] * Py
                 + sh[O_M3 + 2 * 65 + 32 + lane] * Pz + sh[O_M3 + 3 * 65 + 32 + lane] * lgr;
        comb[64 + lane] = fmaf(G1, sh[O_M3G + lane], sh[O_M3B + lane]);
        comb[96 + lane] = fmaf(G2, sh[O_M3G + 32 + lane], sh[O_M3B + 32 + lane]);
        __syncwarp();
        // m4 (relu) — f32x2 packed: pair i-dimension; conflict-free LDS.64 weights
        {
            const ulonglong2* c2 = (const ulonglong2*)comb;
            const unsigned long long* wa = (const unsigned long long*)(sh + O_M4A);
            const unsigned long long* wb = (const unsigned long long*)(sh + O_M4B);
            unsigned long long Aacc = 0ull, Bacc = 0ull;
#pragma unroll
            for (int q = 0; q < 32; q++) {
                ulonglong2 cv = c2[q];
                Aacc = ffma2(wa[(2 * q) * 32 + lane], cv.x, Aacc);
                Aacc = ffma2(wa[(2 * q + 1) * 32 + lane], cv.y, Aacc);
                Bacc = ffma2(wb[(2 * q) * 32 + lane], cv.x, Bacc);
                Bacc = ffma2(wb[(2 * q + 1) * 32 + lane], cv.y, Bacc);
            }
            float2 ua = unpack2(Aacc), ub = unpack2(Bacc);
            float B1 = ua.x + ua.y, B2 = ub.x + ub.y;
            out[((size_t)b * 64 + lane) * NN + n]      = fmaxf(fmaf(B1, sh[O_M4G + lane], sh[O_M4BI + lane]), 0.f);
            out[((size_t)b * 64 + 32 + lane) * NN + n] = fmaxf(fmaf(B2, sh[O_M4G + 32 + lane], sh[O_M4BI + 32 + lane]), 0.f);
        }
        __syncwarp();
    }
}

// -------------------------------- launcher --------------------------------------
extern "C" void kernel_launch(void* const* d_in, const int* in_sizes, int n_in,
                              void* d_out, int out_size)
{
    const float* feature = (const float*)d_in[0];
    const float* xyz     = (const float*)d_in[1];
    const float* m1W  = (const float*)d_in[2];
    const float* m1g  = (const float*)d_in[3];
    const float* m1b  = (const float*)d_in[4];
    const float* lm1W = (const float*)d_in[5];
    const float* lm1g = (const float*)d_in[6];
    const float* lm1b = (const float*)d_in[7];
    const float* lm2W = (const float*)d_in[8];
    const float* lm2g = (const float*)d_in[9];
    const float* lm2b = (const float*)d_in[10];
    const float* p1fcW= (const float*)d_in[11];
    const float* p1mW = (const float*)d_in[12];
    const float* p1mg = (const float*)d_in[13];
    const float* p1mb = (const float*)d_in[14];
    const float* p2fcW= (const float*)d_in[15];
    const float* p2mW = (const float*)d_in[16];
    const float* p2mg = (const float*)d_in[17];
    const float* p2mb = (const float*)d_in[18];
    const float* m2W  = (const float*)d_in[19];
    const float* m2g  = (const float*)d_in[20];
    const float* m2b  = (const float*)d_in[21];
    const float* scW  = (const float*)d_in[22];
    const float* scg  = (const float*)d_in[23];
    const float* scb  = (const float*)d_in[24];
    const float* m3W  = (const float*)d_in[25];
    const float* m3g  = (const float*)d_in[26];
    const float* m3b  = (const float*)d_in[27];
    const float* m4W  = (const float*)d_in[28];
    const float* m4g  = (const float*)d_in[29];
    const float* m4b  = (const float*)d_in[30];
    const int*   nidx = (const int*)d_in[31];
    float* out = (float*)d_out;

    static bool attr_done = false;
    if (!attr_done) {
        cudaFuncSetAttribute(kC, cudaFuncAttributeMaxDynamicSharedMemorySize,
                             SMEM_C_FLOATS * (int)sizeof(float));
        attr_done = true;
    }

    kA<<<(BN + 255) / 256, 256>>>(feature, m1W, m1g, m1b);
    kB<<<1184, 256>>>(xyz, nidx, lm1W, lm1g, lm1b, p1fcW, p1mW, p1mg, p1mb);
    kC<<<296, 256, SMEM_C_FLOATS * sizeof(float)>>>(
        feature, xyz, nidx,
        lm2W, lm2g, lm2b, p2fcW, p2mW, p2mg, p2mb,
        m2W, m2g, m2b, scW, scg, scb, m3W, m3g, m3b, m4W, m4g, m4b, out);
}

// round 11
// speedup vs baseline: 1.2264x; 1.1713x over previous
#include <cuda_runtime.h>
#include <math.h>

#define BB 4
#define NN 20480
#define KK 16
#define BN (BB*NN)   // 81920 points

// ---------------- scratch (__device__ globals; no allocation allowed) ----------
__device__ float g_feat0[BN*16];
__device__ float g_feat1[BN*16];
__device__ float g_lrep[(size_t)BN*256];   // [p][k][c] 83.9MB
__device__ float g_gdis[BN*16];            // [p][k]
__device__ float g_lgr[BN];                // [p]
// folded tail matrices (packed f32x2 channel pairs: [(c*32+l)*2+h] = E[l+32h][c])
__device__ float g_E1p[2048];   // 64x32 via tmp
__device__ float g_E2p[1024];   // 64x16 via feature
__device__ float g_E3p[256];    // 64x4  via [xyz,lgr]
__device__ float g_e0p[64];
__device__ float g_g4p[64];
__device__ float g_b4p[64];

// ---------------- packed f32x2 helpers ------------------------------------------
__device__ __forceinline__ unsigned long long ffma2(unsigned long long a,
                                                    unsigned long long b,
                                                    unsigned long long c)
{
    unsigned long long d;
    asm("fma.rn.f32x2 %0, %1, %2, %3;" : "=l"(d) : "l"(a), "l"(b), "l"(c));
    return d;
}
__device__ __forceinline__ unsigned long long pack2(float x)
{
    unsigned long long d;
    asm("mov.b64 %0, {%1, %1};" : "=l"(d) : "f"(x));
    return d;
}
__device__ __forceinline__ float2 unpack2(unsigned long long v)
{
    float lo, hi;
    asm("mov.b64 {%0, %1}, %2;" : "=f"(lo), "=f"(hi) : "l"(v));
    return make_float2(lo, hi);
}

// ---------------- Kernel Setup: fold linear tail --------------------------------
__global__ void kSetup(const float* __restrict__ m4W,
                       const float* __restrict__ m2W, const float* __restrict__ m2g, const float* __restrict__ m2b,
                       const float* __restrict__ scW, const float* __restrict__ scg, const float* __restrict__ scb,
                       const float* __restrict__ m3W, const float* __restrict__ m3g, const float* __restrict__ m3b,
                       const float* __restrict__ m4g, const float* __restrict__ m4b)
{
    int t = blockIdx.x * blockDim.x + threadIdx.x;
    if (t < 2048) {                       // E1[o][c], c in [0,32)
        int o = t & 63, c = t >> 6;
        float s = 0.f;
        for (int j = 0; j < 64; j++) s += m4W[o * 128 + j] * m2g[j] * m2W[j * 32 + c];
        g_E1p[(c * 32 + (o & 31)) * 2 + (o >> 5)] = s;
    } else if (t < 3072) {                // E2[o][c], c in [0,16)
        int u = t - 2048; int o = u & 63, c = u >> 6;
        float s = 0.f;
        for (int j = 0; j < 64; j++) s += m4W[o * 128 + j] * scg[j] * scW[j * 16 + c];
        g_E2p[(c * 32 + (o & 31)) * 2 + (o >> 5)] = s;
    } else if (t < 3328) {                // E3[o][c], c in [0,4)
        int u = t - 3072; int o = u & 63, c = u >> 6;
        float s = 0.f;
        for (int j = 0; j < 64; j++) s += m4W[o * 128 + 64 + j] * m3g[j] * m3W[j * 4 + c];
        g_E3p[(c * 32 + (o & 31)) * 2 + (o >> 5)] = s;
    } else if (t < 3392) {                // e0[o], g4, b4 packed
        int o = t - 3328;
        float s = 0.f;
        for (int j = 0; j < 64; j++)
            s += m4W[o * 128 + j] * (m2b[j] + scb[j]) + m4W[o * 128 + 64 + j] * m3b[j];
        g_e0p[(o & 31) * 2 + (o >> 5)] = s;
        g_g4p[(o & 31) * 2 + (o >> 5)] = m4g[o];
        g_b4p[(o & 31) * 2 + (o >> 5)] = m4b[o];
    }
}

// ---------------- Kernel A: feat0 = relu(g*(m1_W @ feature)+b) ------------------
__global__ void __launch_bounds__(256) kA(const float* __restrict__ feature,
                                          const float* __restrict__ W,
                                          const float* __restrict__ g,
                                          const float* __restrict__ bia)
{
    __shared__ float sW[256], sg[16], sb[16];
    int tid = threadIdx.x;
    sW[tid] = W[tid];
    if (tid < 16) { sg[tid] = g[tid]; sb[tid] = bia[tid]; }
    __syncthreads();
    int p = blockIdx.x * 256 + tid;
    if (p >= BN) return;
    int b = p / NN, n = p - b * NN;
    const float* f = feature + (size_t)b * 16 * NN + n;
    float x[16];
#pragma unroll
    for (int c = 0; c < 16; c++) x[c] = f[(size_t)c * NN];
#pragma unroll
    for (int o = 0; o < 16; o++) {
        float a = 0.f;
#pragma unroll
        for (int c = 0; c < 16; c++) a = fmaf(sW[o * 16 + c], x[c], a);
        g_feat0[(size_t)p * 16 + o] = fmaxf(fmaf(a, sg[o], sb[o]), 0.f);
    }
}

// -------- attention pool for one lane (= one output channel c of 32) ------------
// cat layout: [34 rows][16 k] (16B-aligned); fcT: transposed weights [34][33-pad]
// K-dimension packed in f32x2: acc[t] holds k=2t,2t+1.
__device__ __forceinline__ float pool_lane(const float* __restrict__ cat,
                                           const float* __restrict__ fcT, int c)
{
    unsigned long long acc[8];
#pragma unroll
    for (int t = 0; t < 8; t++) acc[t] = 0ull;
#pragma unroll
    for (int i = 0; i < 34; i++) {
        unsigned long long w2 = pack2(fcT[i * 33 + c]);
        const ulonglong2* row = (const ulonglong2*)(cat + i * 16);
        ulonglong2 r0 = row[0], r1 = row[1], r2 = row[2], r3 = row[3];
        acc[0] = ffma2(w2, r0.x, acc[0]); acc[1] = ffma2(w2, r0.y, acc[1]);
        acc[2] = ffma2(w2, r1.x, acc[2]); acc[3] = ffma2(w2, r1.y, acc[3]);
        acc[4] = ffma2(w2, r2.x, acc[4]); acc[5] = ffma2(w2, r2.y, acc[5]);
        acc[6] = ffma2(w2, r3.x, acc[6]); acc[7] = ffma2(w2, r3.y, acc[7]);
    }
    float a[16];
#pragma unroll
    for (int t = 0; t < 8; t++) { float2 u = unpack2(acc[t]); a[2*t] = u.x; a[2*t+1] = u.y; }
    float m = a[0];
#pragma unroll
    for (int t = 1; t < 16; t++) m = fmaxf(m, a[t]);
    float s = 0.f;
#pragma unroll
    for (int t = 0; t < 16; t++) { a[t] = __expf(a[t] - m); s += a[t]; }
    const float4* fr = (const float4*)(cat + (2 + c) * 16);
    float4 f0 = fr[0], f1 = fr[1], f2 = fr[2], f3 = fr[3];
    float fl = a[0] * f0.x + a[1] * f0.y + a[2]  * f0.z + a[3]  * f0.w
             + a[4] * f1.x + a[5] * f1.y + a[6]  * f1.z + a[7]  * f1.w
             + a[8] * f2.x + a[9] * f2.y + a[10] * f2.z + a[11] * f2.w
             + a[12]* f3.x + a[13]* f3.y + a[14] * f3.z + a[15] * f3.w;
    return fl / s;
}

// ---------------- Kernel B: geometry + lrep + pool1 -> feat1 --------------------
#define WB 8
__global__ void __launch_bounds__(256, 4) kB(
    const float* __restrict__ xyz, const int* __restrict__ nidx,
    const float* __restrict__ lm1W, const float* __restrict__ lm1g, const float* __restrict__ lm1b,
    const float* __restrict__ fcW,
    const float* __restrict__ pmW, const float* __restrict__ pmg, const float* __restrict__ pmb)
{
    __shared__ float sLW[144], sLg[16], sLb[16];
    __shared__ float sFc[34 * 33];
    __shared__ float sPm[32 * 17];
    __shared__ float sPg[16], sPb[16];
    __shared__ __align__(16) float sCat[WB][544];
    __shared__ __align__(16) float sFlc[WB][32];

    int tid = threadIdx.x;
    for (int t = tid; t < 144; t += 256) sLW[t] = lm1W[t];
    if (tid < 16) { sLg[tid] = lm1g[tid]; sLb[tid] = lm1b[tid];
                    sPg[tid] = pmg[tid];  sPb[tid] = pmb[tid]; }
    for (int t = tid; t < 1088; t += 256) { int o = t / 34, i = t - o * 34; sFc[i * 33 + o] = fcW[t]; }
    for (int t = tid; t < 512;  t += 256) { int o = t >> 5, c = t & 31;     sPm[c * 17 + o] = pmW[t]; }
    __syncthreads();

    int warp = tid >> 5, lane = tid & 31;
    int k = lane & 15, h = lane >> 4, cbase = h * 8;
    float* cat = sCat[warp];
    float* flc = sFlc[warp];
    int nwarps = gridDim.x * WB;
    for (int p = blockIdx.x * WB + warp; p < BN; p += nwarps) {
        int b = p / NN;
        float Px = xyz[(size_t)p * 3 + 0], Py = xyz[(size_t)p * 3 + 1], Pz = xyz[(size_t)p * 3 + 2];
        int idx = nidx[(size_t)p * 16 + k];
        int nbp = b * NN + idx;
        float Qx = xyz[(size_t)nbp * 3 + 0], Qy = xyz[(size_t)nbp * 3 + 1], Qz = xyz[(size_t)nbp * 3 + 2];
        float rx = Px - Qx, ry = Py - Qy, rz = Pz - Qz;
        float rxy2 = rx * rx + ry * ry;
        float rd = sqrtf(rxy2 + rz * rz);
        float ral = atan2f(ry, rx);
        float rbe = atan2f(rz, sqrtf(rxy2));
        float gd = __expf(-rd);
        // 16-lane reductions (halves hold duplicate k-data; offsets <=8 stay in-half)
        float maxd = rd, sx = Qx, sy = Qy, sz = Qz;
#pragma unroll
        for (int off = 8; off; off >>= 1) {
            maxd = fmaxf(maxd, __shfl_xor_sync(0xffffffffu, maxd, off));
            sx += __shfl_xor_sync(0xffffffffu, sx, off);
            sy += __shfl_xor_sync(0xffffffffu, sy, off);
            sz += __shfl_xor_sync(0xffffffffu, sz, off);
        }
        float dvx = Px - sx * (1.f / 16.f), dvy = Py - sy * (1.f / 16.f), dvz = Pz - sz * (1.f / 16.f);
        float dal = atan2f(dvy, dvx);
        float dbe = atan2f(dvz, sqrtf(dvx * dvx + dvy * dvy));
        float rep[9] = { ral - dal, rbe - dbe, rd, Px, Py, Pz, Qx, Qy, Qz };
        float lrv[8];
#pragma unroll
        for (int j = 0; j < 8; j++) {
            int c = cbase + j;
            float a = 0.f;
#pragma unroll
            for (int i = 0; i < 9; i++) a = fmaf(sLW[c * 9 + i], rep[i], a);
            float v = fmaxf(fmaf(a, sLg[c], sLb[c]), 0.f);
            lrv[j] = v;
            cat[(18 + c) * 16 + k] = v;
        }
        {
            float4* dst = (float4*)(g_lrep + (size_t)p * 256 + k * 16 + cbase);
            dst[0] = make_float4(lrv[0], lrv[1], lrv[2], lrv[3]);
            dst[1] = make_float4(lrv[4], lrv[5], lrv[6], lrv[7]);
        }
        if (h == 0) { cat[k] = gd; g_gdis[(size_t)p * 16 + k] = gd; }
        if (lane == 0) {
            float gn2 = Px * Px + Py * Py + Pz * Pz;
            g_lgr[p] = (maxd * maxd * maxd) / (gn2 * sqrtf(gn2));
        }
        // feat0 gather + f_dis
        const float4* fq = (const float4*)(g_feat0 + (size_t)nbp * 16 + cbase);
        float4 a0 = fq[0], a1 = fq[1];
        const float4* fp4 = (const float4*)(g_feat0 + (size_t)p * 16 + cbase);
        float4 c0 = fp4[0], c1 = fp4[1];
        float pa = fabsf(a0.x - c0.x) + fabsf(a0.y - c0.y) + fabsf(a0.z - c0.z) + fabsf(a0.w - c0.w)
                 + fabsf(a1.x - c1.x) + fabsf(a1.y - c1.y) + fabsf(a1.z - c1.z) + fabsf(a1.w - c1.w);
        pa += __shfl_xor_sync(0xffffffffu, pa, 16);
        if (h == 0) cat[16 + k] = __expf(-pa * (1.f / 16.f)) * 2.0f;  // f_dis * LAMDA
        cat[(2 + cbase + 0) * 16 + k] = a0.x; cat[(2 + cbase + 1) * 16 + k] = a0.y;
        cat[(2 + cbase + 2) * 16 + k] = a0.z; cat[(2 + cbase + 3) * 16 + k] = a0.w;
        cat[(2 + cbase + 4) * 16 + k] = a1.x; cat[(2 + cbase + 5) * 16 + k] = a1.y;
        cat[(2 + cbase + 6) * 16 + k] = a1.z; cat[(2 + cbase + 7) * 16 + k] = a1.w;
        __syncwarp();
        float fl = pool_lane(cat, sFc, lane);
        flc[lane] = fl;
        __syncwarp();
        if (lane < 16) {
            float a = 0.f;
#pragma unroll
            for (int c = 0; c < 32; c++) a = fmaf(sPm[c * 17 + lane], flc[c], a);
            g_feat1[(size_t)p * 16 + lane] = fmaxf(fmaf(a, sPg[lane], sPb[lane]), 0.f);
        }
        __syncwarp();
    }
}

// ---------------- Kernel C: lrep2 + pool2 + p2m + folded tail -------------------
#define WC 8
// shared layout (float offsets)
#define O_LM2W 0
#define O_LM2G 256
#define O_LM2B 272
#define O_FC2  288      /* 34*33 = 1122 */
#define O_P2M  1410     /* 32*33 = 1056 */
#define O_P2G  2466
#define O_P2B  2498
#define O_E1   2532     /* 2048 */
#define O_E2   4580     /* 1024 */
#define O_E3   5604     /* 256 */
#define O_E0   5860     /* 64 packed */
#define O_G4   5924     /* 64 packed */
#define O_B4   5988     /* 64 packed */
#define O_WARP 6052
#define WSTRIDE 624     /* cat 544 + flc 32 + tmp 32 + pf 16 */
#define SMEM_C_FLOATS (O_WARP + WC * WSTRIDE)   /* 11044 floats = 44176 B */

__global__ void __launch_bounds__(256, 4) kC(
    const float* __restrict__ feature, const float* __restrict__ xyz, const int* __restrict__ nidx,
    const float* __restrict__ lm2W, const float* __restrict__ lm2g, const float* __restrict__ lm2b,
    const float* __restrict__ fc2W,
    const float* __restrict__ p2mW, const float* __restrict__ p2mg, const float* __restrict__ p2mb,
    float* __restrict__ out)
{
    extern __shared__ float sh[];
    int tid = threadIdx.x;
    for (int t = tid; t < 256;  t += 256) sh[O_LM2W + t] = lm2W[t];
    for (int t = tid; t < 16;   t += 256) { sh[O_LM2G + t] = lm2g[t]; sh[O_LM2B + t] = lm2b[t]; }
    for (int t = tid; t < 1088; t += 256) { int o = t / 34, i = t - o * 34; sh[O_FC2 + i * 33 + o] = fc2W[t]; }
    for (int t = tid; t < 1024; t += 256) { int o = t >> 5, c = t & 31; sh[O_P2M + c * 33 + o] = p2mW[t]; }
    for (int t = tid; t < 32;   t += 256) { sh[O_P2G + t] = p2mg[t]; sh[O_P2B + t] = p2mb[t]; }
    for (int t = tid; t < 2048; t += 256) sh[O_E1 + t] = g_E1p[t];
    for (int t = tid; t < 1024; t += 256) sh[O_E2 + t] = g_E2p[t];
    for (int t = tid; t < 256;  t += 256) sh[O_E3 + t] = g_E3p[t];
    if (tid < 64) { sh[O_E0 + tid] = g_e0p[tid]; sh[O_G4 + tid] = g_g4p[tid]; sh[O_B4 + tid] = g_b4p[tid]; }
    __syncthreads();

    int warp = tid >> 5, lane = tid & 31, k = lane & 15, h = lane >> 4, cbase = h * 8;
    float* wsh  = sh + O_WARP + warp * WSTRIDE;
    float* cat  = wsh;
    float* flc  = wsh + 544;
    float* tmp  = wsh + 576;
    float* pf   = wsh + 608;
    const unsigned long long* e1 = (const unsigned long long*)(sh + O_E1);
    const unsigned long long* e2 = (const unsigned long long*)(sh + O_E2);
    const unsigned long long* e3 = (const unsigned long long*)(sh + O_E3);
    int nwarps = gridDim.x * WC;
    for (int p = blockIdx.x * WC + warp; p < BN; p += nwarps) {
        int b = p / NN, n = p - b * NN;
        const float4* lq = (const float4*)(g_lrep + (size_t)p * 256 + k * 16);
        float4 L0 = lq[0], L1 = lq[1], L2 = lq[2], L3 = lq[3];
        float lr[16] = { L0.x, L0.y, L0.z, L0.w, L1.x, L1.y, L1.z, L1.w,
                         L2.x, L2.y, L2.z, L2.w, L3.x, L3.y, L3.z, L3.w };
#pragma unroll
        for (int j = 0; j < 8; j++) {
            int c = cbase + j;
            float a = 0.f;
#pragma unroll
            for (int i = 0; i < 16; i++) a = fmaf(sh[O_LM2W + c * 16 + i], lr[i], a);
            cat[(18 + c) * 16 + k] = fmaxf(fmaf(a, sh[O_LM2G + c], sh[O_LM2B + c]), 0.f);
        }
        if (h == 0) cat[k] = g_gdis[(size_t)p * 16 + k];
        int idx = nidx[(size_t)p * 16 + k];
        int nbp = b * NN + idx;
        const float4* fq = (const float4*)(g_feat1 + (size_t)nbp * 16 + cbase);
        float4 a0 = fq[0], a1 = fq[1];
        const float4* fp4 = (const float4*)(g_feat1 + (size_t)p * 16 + cbase);
        float4 c0 = fp4[0], c1 = fp4[1];
        float pa = fabsf(a0.x - c0.x) + fabsf(a0.y - c0.y) + fabsf(a0.z - c0.z) + fabsf(a0.w - c0.w)
                 + fabsf(a1.x - c1.x) + fabsf(a1.y - c1.y) + fabsf(a1.z - c1.z) + fabsf(a1.w - c1.w);
        pa += __shfl_xor_sync(0xffffffffu, pa, 16);
        if (h == 0) cat[16 + k] = __expf(-pa * (1.f / 16.f)) * 2.0f;
        cat[(2 + cbase + 0) * 16 + k] = a0.x; cat[(2 + cbase + 1) * 16 + k] = a0.y;
        cat[(2 + cbase + 2) * 16 + k] = a0.z; cat[(2 + cbase + 3) * 16 + k] = a0.w;
        cat[(2 + cbase + 4) * 16 + k] = a1.x; cat[(2 + cbase + 5) * 16 + k] = a1.y;
        cat[(2 + cbase + 6) * 16 + k] = a1.z; cat[(2 + cbase + 7) * 16 + k] = a1.w;
        if (lane < 16) pf[lane] = feature[(size_t)b * 16 * NN + (size_t)lane * NN + n];
        __syncwarp();
        float fl = pool_lane(cat, sh + O_FC2, lane);
        flc[lane] = fl;
        __syncwarp();
        {   // p2m (relu)
            float a = 0.f;
#pragma unroll
            for (int c = 0; c < 32; c++) a = fmaf(sh[O_P2M + c * 33 + lane], flc[c], a);
            tmp[lane] = fmaxf(fmaf(a, sh[O_P2G + lane], sh[O_P2B + lane]), 0.f);
        }
        __syncwarp();
        // folded tail: out = relu(g4*(E1@tmp + E2@pf + E3@u + e0) + b4), 2 ch/lane f32x2
        {
            unsigned long long acc = ((const unsigned long long*)(sh + O_E0))[lane];
#pragma unroll
            for (int c = 0; c < 32; c++) acc = ffma2(e1[c * 32 + lane], pack2(tmp[c]), acc);
#pragma unroll
            for (int c = 0; c < 16; c++) acc = ffma2(e2[c * 32 + lane], pack2(pf[c]), acc);
            float Px = xyz[(size_t)p * 3], Py = xyz[(size_t)p * 3 + 1], Pz = xyz[(size_t)p * 3 + 2];
            float lgr = g_lgr[p];
            acc = ffma2(e3[0 * 32 + lane], pack2(Px), acc);
            acc = ffma2(e3[1 * 32 + lane], pack2(Py), acc);
            acc = ffma2(e3[2 * 32 + lane], pack2(Pz), acc);
            acc = ffma2(e3[3 * 32 + lane], pack2(lgr), acc);
            unsigned long long g4 = ((const unsigned long long*)(sh + O_G4))[lane];
            unsigned long long b4 = ((const unsigned long long*)(sh + O_B4))[lane];
            float2 o2 = unpack2(ffma2(acc, g4, b4));
            out[((size_t)b * 64 + lane) * NN + n]      = fmaxf(o2.x, 0.f);
            out[((size_t)b * 64 + 32 + lane) * NN + n] = fmaxf(o2.y, 0.f);
        }
        __syncwarp();
    }
}

// -------------------------------- launcher --------------------------------------
extern "C" void kernel_launch(void* const* d_in, const int* in_sizes, int n_in,
                              void* d_out, int out_size)
{
    const float* feature = (const float*)d_in[0];
    const float* xyz     = (const float*)d_in[1];
    const float* m1W  = (const float*)d_in[2];
    const float* m1g  = (const float*)d_in[3];
    const float* m1b  = (const float*)d_in[4];
    const float* lm1W = (const float*)d_in[5];
    const float* lm1g = (const float*)d_in[6];
    const float* lm1b = (const float*)d_in[7];
    const float* lm2W = (const float*)d_in[8];
    const float* lm2g = (const float*)d_in[9];
    const float* lm2b = (const float*)d_in[10];
    const float* p1fcW= (const float*)d_in[11];
    const float* p1mW = (const float*)d_in[12];
    const float* p1mg = (const float*)d_in[13];
    const float* p1mb = (const float*)d_in[14];
    const float* p2fcW= (const float*)d_in[15];
    const float* p2mW = (const float*)d_in[16];
    const float* p2mg = (const float*)d_in[17];
    const float* p2mb = (const float*)d_in[18];
    const float* m2W  = (const float*)d_in[19];
    const float* m2g  = (const float*)d_in[20];
    const float* m2b  = (const float*)d_in[21];
    const float* scW  = (const float*)d_in[22];
    const float* scg  = (const float*)d_in[23];
    const float* scb  = (const float*)d_in[24];
    const float* m3W  = (const float*)d_in[25];
    const float* m3g  = (const float*)d_in[26];
    const float* m3b  = (const float*)d_in[27];
    const float* m4W  = (const float*)d_in[28];
    const float* m4g  = (const float*)d_in[29];
    const float* m4b  = (const float*)d_in[30];
    const int*   nidx = (const int*)d_in[31];
    float* out = (float*)d_out;

    static bool attr_done = false;
    if (!attr_done) {
        cudaFuncSetAttribute(kC, cudaFuncAttributeMaxDynamicSharedMemorySize,
                             SMEM_C_FLOATS * (int)sizeof(float));
        attr_done = true;
    }

    kSetup<<<7, 512>>>(m4W, m2W, m2g, m2b, scW, scg, scb, m3W, m3g, m3b, m4g, m4b);
    kA<<<(BN + 255) / 256, 256>>>(feature, m1W, m1g, m1b);
    kB<<<1184, 256>>>(xyz, nidx, lm1W, lm1g, lm1b, p1fcW, p1mW, p1mg, p1mb);
    kC<<<592, 256, SMEM_C_FLOATS * sizeof(float)>>>(
        feature, xyz, nidx,
        lm2W, lm2g, lm2b, p2fcW, p2mW, p2mg, p2mb, out);
}

// round 13
// speedup vs baseline: 1.4089x; 1.1488x over previous
#include <cuda_runtime.h>
#include <math.h>

#define BB 4
#define NN 20480
#define KK 16
#define BN (BB*NN)   // 81920 points
#define CAT_S 20     // padded cat row stride (floats): 16B-aligned, kills 16-way conflict

// ---------------- scratch (__device__ globals; no allocation allowed) ----------
__device__ float g_feat0[BN*16];
__device__ float g_feat1[BN*16];
__device__ float g_lrep[(size_t)BN*256];   // [p][k][c]
__device__ float g_gdis[BN*16];            // [p][k]
__device__ float g_lgr[BN];                // [p]
__device__ float g_tmp2[(size_t)BN*32];    // p2m output, [p][32]
// folded tail: Ecat[o][52] (c<32: via tmp, 32..47: via feature, 48..51: via xyz/lgr)
__device__ float g_Ecat[64*52];
__device__ float g_e0[64];
__device__ float g_g4[64];
__device__ float g_b4[64];

// ---------------- packed f32x2 helpers ------------------------------------------
__device__ __forceinline__ unsigned long long ffma2(unsigned long long a,
                                                    unsigned long long b,
                                                    unsigned long long c)
{
    unsigned long long d;
    asm("fma.rn.f32x2 %0, %1, %2, %3;" : "=l"(d) : "l"(a), "l"(b), "l"(c));
    return d;
}
__device__ __forceinline__ unsigned long long pack2(float x)
{
    unsigned long long d;
    asm("mov.b64 %0, {%1, %1};" : "=l"(d) : "f"(x));
    return d;
}
__device__ __forceinline__ unsigned long long pack2f(float lo, float hi)
{
    unsigned long long d;
    asm("mov.b64 %0, {%1, %2};" : "=l"(d) : "f"(lo), "f"(hi));
    return d;
}
__device__ __forceinline__ float2 unpack2(unsigned long long v)
{
    float lo, hi;
    asm("mov.b64 {%0, %1}, %2;" : "=f"(lo), "=f"(hi) : "l"(v));
    return make_float2(lo, hi);
}

// ---------------- Kernel Setup: fold linear tail into Ecat ----------------------
__global__ void kSetup(const float* __restrict__ m4W,
                       const float* __restrict__ m2W, const float* __restrict__ m2g, const float* __restrict__ m2b,
                       const float* __restrict__ scW, const float* __restrict__ scg, const float* __restrict__ scb,
                       const float* __restrict__ m3W, const float* __restrict__ m3g, const float* __restrict__ m3b,
                       const float* __restrict__ m4g, const float* __restrict__ m4b)
{
    int t = blockIdx.x * blockDim.x + threadIdx.x;
    if (t < 3328) {
        int o = t / 52, c = t % 52;
        float s = 0.f;
        if (c < 32) {
            for (int j = 0; j < 64; j++) s += m4W[o * 128 + j] * m2g[j] * m2W[j * 32 + c];
        } else if (c < 48) {
            int cc = c - 32;
            for (int j = 0; j < 64; j++) s += m4W[o * 128 + j] * scg[j] * scW[j * 16 + cc];
        } else {
            int cc = c - 48;
            for (int j = 0; j < 64; j++) s += m4W[o * 128 + 64 + j] * m3g[j] * m3W[j * 4 + cc];
        }
        g_Ecat[o * 52 + c] = s;
    } else if (t < 3392) {
        int o = t - 3328;
        float s = 0.f;
        for (int j = 0; j < 64; j++)
            s += m4W[o * 128 + j] * (m2b[j] + scb[j]) + m4W[o * 128 + 64 + j] * m3b[j];
        g_e0[o] = s;
        g_g4[o] = m4g[o];
        g_b4[o] = m4b[o];
    }
}

// ---------------- Kernel A: feat0 = relu(g*(m1_W @ feature)+b) ------------------
__global__ void __launch_bounds__(256) kA(const float* __restrict__ feature,
                                          const float* __restrict__ W,
                                          const float* __restrict__ g,
                                          const float* __restrict__ bia)
{
    __shared__ float sW[256], sg[16], sb[16];
    int tid = threadIdx.x;
    sW[tid] = W[tid];
    if (tid < 16) { sg[tid] = g[tid]; sb[tid] = bia[tid]; }
    __syncthreads();
    int p = blockIdx.x * 256 + tid;
    if (p >= BN) return;
    int b = p / NN, n = p - b * NN;
    const float* f = feature + (size_t)b * 16 * NN + n;
    float x[16];
#pragma unroll
    for (int c = 0; c < 16; c++) x[c] = f[(size_t)c * NN];
#pragma unroll
    for (int o = 0; o < 16; o++) {
        float a = 0.f;
#pragma unroll
        for (int c = 0; c < 16; c++) a = fmaf(sW[o * 16 + c], x[c], a);
        g_feat0[(size_t)p * 16 + o] = fmaxf(fmaf(a, sg[o], sb[o]), 0.f);
    }
}

// -------- attention pool for one lane (= one output channel c of 32) ------------
// cat layout: [34 rows][CAT_S stride, 16 valid k]; fcT: transposed [34][33-pad]
__device__ __forceinline__ float pool_lane(const float* __restrict__ cat,
                                           const float* __restrict__ fcT, int c)
{
    unsigned long long acc[8];
#pragma unroll
    for (int t = 0; t < 8; t++) acc[t] = 0ull;
#pragma unroll
    for (int i = 0; i < 34; i++) {
        unsigned long long w2 = pack2(fcT[i * 33 + c]);
        const ulonglong2* row = (const ulonglong2*)(cat + i * CAT_S);
        ulonglong2 r0 = row[0], r1 = row[1], r2 = row[2], r3 = row[3];
        acc[0] = ffma2(w2, r0.x, acc[0]); acc[1] = ffma2(w2, r0.y, acc[1]);
        acc[2] = ffma2(w2, r1.x, acc[2]); acc[3] = ffma2(w2, r1.y, acc[3]);
        acc[4] = ffma2(w2, r2.x, acc[4]); acc[5] = ffma2(w2, r2.y, acc[5]);
        acc[6] = ffma2(w2, r3.x, acc[6]); acc[7] = ffma2(w2, r3.y, acc[7]);
    }
    float a[16];
#pragma unroll
    for (int t = 0; t < 8; t++) { float2 u = unpack2(acc[t]); a[2*t] = u.x; a[2*t+1] = u.y; }
    float m = a[0];
#pragma unroll
    for (int t = 1; t < 16; t++) m = fmaxf(m, a[t]);
    float s = 0.f;
#pragma unroll
    for (int t = 0; t < 16; t++) { a[t] = __expf(a[t] - m); s += a[t]; }
    const float4* fr = (const float4*)(cat + (2 + c) * CAT_S);
    float4 f0 = fr[0], f1 = fr[1], f2 = fr[2], f3 = fr[3];
    float fl = a[0] * f0.x + a[1] * f0.y + a[2]  * f0.z + a[3]  * f0.w
             + a[4] * f1.x + a[5] * f1.y + a[6]  * f1.z + a[7]  * f1.w
             + a[8] * f2.x + a[9] * f2.y + a[10] * f2.z + a[11] * f2.w
             + a[12]* f3.x + a[13]* f3.y + a[14] * f3.z + a[15] * f3.w;
    return fl / s;
}

// ---------------- Kernel B: geometry + lrep + pool1 -> feat1 --------------------
#define WB 8
__global__ void __launch_bounds__(256, 4) kB(
    const float* __restrict__ xyz, const int* __restrict__ nidx,
    const float* __restrict__ lm1W, const float* __restrict__ lm1g, const float* __restrict__ lm1b,
    const float* __restrict__ fcW,
    const float* __restrict__ pmW, const float* __restrict__ pmg, const float* __restrict__ pmb)
{
    __shared__ float sLW[144], sLg[16], sLb[16];
    __shared__ float sFc[34 * 33];
    __shared__ float sPm[32 * 17];
    __shared__ float sPg[16], sPb[16];
    __shared__ __align__(16) float sCat[WB][34 * CAT_S];
    __shared__ __align__(16) float sFlc[WB][32];

    int tid = threadIdx.x;
    for (int t = tid; t < 144; t += 256) sLW[t] = lm1W[t];
    if (tid < 16) { sLg[tid] = lm1g[tid]; sLb[tid] = lm1b[tid];
                    sPg[tid] = pmg[tid];  sPb[tid] = pmb[tid]; }
    for (int t = tid; t < 1088; t += 256) { int o = t / 34, i = t - o * 34; sFc[i * 33 + o] = fcW[t]; }
    for (int t = tid; t < 512;  t += 256) { int o = t >> 5, c = t & 31;     sPm[c * 17 + o] = pmW[t]; }
    __syncthreads();

    int warp = tid >> 5, lane = tid & 31;
    int k = lane & 15, h = lane >> 4, cbase = h * 8;
    float* cat = sCat[warp];
    float* flc = sFlc[warp];
    int nwarps = gridDim.x * WB;
    for (int p = blockIdx.x * WB + warp; p < BN; p += nwarps) {
        int b = p / NN;
        float Px = xyz[(size_t)p * 3 + 0], Py = xyz[(size_t)p * 3 + 1], Pz = xyz[(size_t)p * 3 + 2];
        int idx = nidx[(size_t)p * 16 + k];
        int nbp = b * NN + idx;
        float Qx = xyz[(size_t)nbp * 3 + 0], Qy = xyz[(size_t)nbp * 3 + 1], Qz = xyz[(size_t)nbp * 3 + 2];
        float rx = Px - Qx, ry = Py - Qy, rz = Pz - Qz;
        float rxy2 = rx * rx + ry * ry;
        float rd = sqrtf(rxy2 + rz * rz);
        float ral = atan2f(ry, rx);
        float rbe = atan2f(rz, sqrtf(rxy2));
        float gd = __expf(-rd);
        float maxd = rd, sx = Qx, sy = Qy, sz = Qz;
#pragma unroll
        for (int off = 8; off; off >>= 1) {
            maxd = fmaxf(maxd, __shfl_xor_sync(0xffffffffu, maxd, off));
            sx += __shfl_xor_sync(0xffffffffu, sx, off);
            sy += __shfl_xor_sync(0xffffffffu, sy, off);
            sz += __shfl_xor_sync(0xffffffffu, sz, off);
        }
        float dvx = Px - sx * (1.f / 16.f), dvy = Py - sy * (1.f / 16.f), dvz = Pz - sz * (1.f / 16.f);
        float dal = atan2f(dvy, dvx);
        float dbe = atan2f(dvz, sqrtf(dvx * dvx + dvy * dvy));
        float rep[9] = { ral - dal, rbe - dbe, rd, Px, Py, Pz, Qx, Qy, Qz };
        float lrv[8];
#pragma unroll
        for (int j = 0; j < 8; j++) {
            int c = cbase + j;
            float a = 0.f;
#pragma unroll
            for (int i = 0; i < 9; i++) a = fmaf(sLW[c * 9 + i], rep[i], a);
            float v = fmaxf(fmaf(a, sLg[c], sLb[c]), 0.f);
            lrv[j] = v;
            cat[(18 + c) * CAT_S + k] = v;
        }
        {
            float4* dst = (float4*)(g_lrep + (size_t)p * 256 + k * 16 + cbase);
            dst[0] = make_float4(lrv[0], lrv[1], lrv[2], lrv[3]);
            dst[1] = make_float4(lrv[4], lrv[5], lrv[6], lrv[7]);
        }
        if (h == 0) { cat[k] = gd; g_gdis[(size_t)p * 16 + k] = gd; }
        if (lane == 0) {
            float gn2 = Px * Px + Py * Py + Pz * Pz;
            g_lgr[p] = (maxd * maxd * maxd) / (gn2 * sqrtf(gn2));
        }
        const float4* fq = (const float4*)(g_feat0 + (size_t)nbp * 16 + cbase);
        float4 a0 = fq[0], a1 = fq[1];
        const float4* fp4 = (const float4*)(g_feat0 + (size_t)p * 16 + cbase);
        float4 c0 = fp4[0], c1 = fp4[1];
        float pa = fabsf(a0.x - c0.x) + fabsf(a0.y - c0.y) + fabsf(a0.z - c0.z) + fabsf(a0.w - c0.w)
                 + fabsf(a1.x - c1.x) + fabsf(a1.y - c1.y) + fabsf(a1.z - c1.z) + fabsf(a1.w - c1.w);
        pa += __shfl_xor_sync(0xffffffffu, pa, 16);
        if (h == 0) cat[CAT_S + k] = __expf(-pa * (1.f / 16.f)) * 2.0f;  // f_dis * LAMDA
        cat[(2 + cbase + 0) * CAT_S + k] = a0.x; cat[(2 + cbase + 1) * CAT_S + k] = a0.y;
        cat[(2 + cbase + 2) * CAT_S + k] = a0.z; cat[(2 + cbase + 3) * CAT_S + k] = a0.w;
        cat[(2 + cbase + 4) * CAT_S + k] = a1.x; cat[(2 + cbase + 5) * CAT_S + k] = a1.y;
        cat[(2 + cbase + 6) * CAT_S + k] = a1.z; cat[(2 + cbase + 7) * CAT_S + k] = a1.w;
        __syncwarp();
        float fl = pool_lane(cat, sFc, lane);
        flc[lane] = fl;
        __syncwarp();
        if (lane < 16) {
            float a = 0.f;
#pragma unroll
            for (int c = 0; c < 32; c++) a = fmaf(sPm[c * 17 + lane], flc[c], a);
            g_feat1[(size_t)p * 16 + lane] = fmaxf(fmaf(a, sPg[lane], sPb[lane]), 0.f);
        }
        __syncwarp();
    }
}

// ---------------- Kernel C: lrep2 + pool2 + p2m -> g_tmp2 -----------------------
#define WC 8
__global__ void __launch_bounds__(256, 4) kC(
    const int* __restrict__ nidx,
    const float* __restrict__ lm2W, const float* __restrict__ lm2g, const float* __restrict__ lm2b,
    const float* __restrict__ fc2W,
    const float* __restrict__ p2mW, const float* __restrict__ p2mg, const float* __restrict__ p2mb)
{
    __shared__ __align__(8) float sLW2[256];  // lm2 row-major [c][16] (pairs along i)
    __shared__ float sLg[16], sLb[16];
    __shared__ float sFc[34 * 33];
    __shared__ __align__(8) float sP2[1024];  // p2m packed [cp][o][2]
    __shared__ float sPg[32], sPb[32];
    __shared__ __align__(16) float sCat[WC][34 * CAT_S];
    __shared__ __align__(16) float sFlc[WC][32];

    int tid = threadIdx.x;
    for (int t = tid; t < 256;  t += 256) sLW2[t] = lm2W[t];
    if (tid < 16) { sLg[tid] = lm2g[tid]; sLb[tid] = lm2b[tid]; }
    for (int t = tid; t < 1088; t += 256) { int o = t / 34, i = t - o * 34; sFc[i * 33 + o] = fc2W[t]; }
    for (int t = tid; t < 1024; t += 256) {
        int cp = t >> 6, o = (t >> 1) & 31, e = t & 1;
        sP2[t] = p2mW[o * 32 + cp * 2 + e];
    }
    if (tid < 32) { sPg[tid] = p2mg[tid]; sPb[tid] = p2mb[tid]; }
    __syncthreads();

    int warp = tid >> 5, lane = tid & 31, k = lane & 15, h = lane >> 4, cbase = h * 8;
    float* cat = sCat[warp];
    float* flc = sFlc[warp];
    const unsigned long long* w2lm = (const unsigned long long*)sLW2;
    const unsigned long long* w2p  = (const unsigned long long*)sP2;
    int nwarps = gridDim.x * WC;
    for (int p = blockIdx.x * WC + warp; p < BN; p += nwarps) {
        int b = p / NN;
        // lrep load as 8 packed f32x2 pairs
        const ulonglong2* lq = (const ulonglong2*)(g_lrep + (size_t)p * 256 + k * 16);
        ulonglong2 M0 = lq[0], M1 = lq[1], M2 = lq[2], M3 = lq[3];
        unsigned long long lr2[8] = { M0.x, M0.y, M1.x, M1.y, M2.x, M2.y, M3.x, M3.y };
        // lrep2 matvec, f32x2 packed over input pairs
#pragma unroll
        for (int j = 0; j < 8; j++) {
            int c = cbase + j;
            unsigned long long acc2 = 0ull;
#pragma unroll
            for (int ip = 0; ip < 8; ip++) acc2 = ffma2(w2lm[c * 8 + ip], lr2[ip], acc2);
            float2 u = unpack2(acc2);
            float a = u.x + u.y;
            cat[(18 + c) * CAT_S + k] = fmaxf(fmaf(a, sLg[c], sLb[c]), 0.f);
        }
        if (h == 0) cat[k] = g_gdis[(size_t)p * 16 + k];
        int idx = nidx[(size_t)p * 16 + k];
        int nbp = b * NN + idx;
        const float4* fq = (const float4*)(g_feat1 + (size_t)nbp * 16 + cbase);
        float4 a0 = fq[0], a1 = fq[1];
        const float4* fp4 = (const float4*)(g_feat1 + (size_t)p * 16 + cbase);
        float4 c0 = fp4[0], c1 = fp4[1];
        float pa = fabsf(a0.x - c0.x) + fabsf(a0.y - c0.y) + fabsf(a0.z - c0.z) + fabsf(a0.w - c0.w)
                 + fabsf(a1.x - c1.x) + fabsf(a1.y - c1.y) + fabsf(a1.z - c1.z) + fabsf(a1.w - c1.w);
        pa += __shfl_xor_sync(0xffffffffu, pa, 16);
        if (h == 0) cat[CAT_S + k] = __expf(-pa * (1.f / 16.f)) * 2.0f;
        cat[(2 + cbase + 0) * CAT_S + k] = a0.x; cat[(2 + cbase + 1) * CAT_S + k] = a0.y;
        cat[(2 + cbase + 2) * CAT_S + k] = a0.z; cat[(2 + cbase + 3) * CAT_S + k] = a0.w;
        cat[(2 + cbase + 4) * CAT_S + k] = a1.x; cat[(2 + cbase + 5) * CAT_S + k] = a1.y;
        cat[(2 + cbase + 6) * CAT_S + k] = a1.z; cat[(2 + cbase + 7) * CAT_S + k] = a1.w;
        __syncwarp();
        float fl = pool_lane(cat, sFc, lane);
        flc[lane] = fl;
        __syncwarp();
        {   // p2m (relu) -> g_tmp2, f32x2 packed over input pairs
            const unsigned long long* f2 = (const unsigned long long*)flc;
            unsigned long long acc2 = 0ull;
#pragma unroll
            for (int cp = 0; cp < 16; cp++) acc2 = ffma2(w2p[cp * 32 + lane], f2[cp], acc2);
            float2 u = unpack2(acc2);
            float a = u.x + u.y;
            g_tmp2[(size_t)p * 32 + lane] = fmaxf(fmaf(a, sPg[lane], sPb[lane]), 0.f);
        }
        __syncwarp();
    }
}

// ---------------- Kernel D: folded tail, lane = point ---------------------------
// out[b][o][n] = relu(g4[o]*(Ecat[o] @ x + e0[o]) + b4[o]), x = [tmp(32), feature(16), xyz, lgr]
__global__ void __launch_bounds__(256) kD(const float* __restrict__ feature,
                                          const float* __restrict__ xyz,
                                          float* __restrict__ out)
{
    __shared__ __align__(8) float sE[64 * 52];
    __shared__ float sE0[64], sG4[64], sB4[64];
    int tid = threadIdx.x;
    for (int t = tid; t < 64 * 52; t += 256) sE[t] = g_Ecat[t];
    if (tid < 64) { sE0[tid] = g_e0[tid]; sG4[tid] = g_g4[tid]; sB4[tid] = g_b4[tid]; }
    __syncthreads();

    int warp = tid >> 5, lane = tid & 31;
    int p = (blockIdx.x * 8 + warp) * 32 + lane;   // grid(320)*8*32 == BN exactly
    int b = p / NN, n = p - b * NN;

    unsigned long long xp[26];
    const ulonglong2* tq = (const ulonglong2*)(g_tmp2 + (size_t)p * 32);
#pragma unroll
    for (int q = 0; q < 8; q++) { ulonglong2 v = tq[q]; xp[2 * q] = v.x; xp[2 * q + 1] = v.y; }
    const float* fb = feature + (size_t)b * 16 * NN + n;
#pragma unroll
    for (int cp = 0; cp < 8; cp++)
        xp[16 + cp] = pack2f(fb[(size_t)(2 * cp) * NN], fb[(size_t)(2 * cp + 1) * NN]);
    float Px = xyz[(size_t)p * 3], Py = xyz[(size_t)p * 3 + 1], Pz = xyz[(size_t)p * 3 + 2];
    xp[24] = pack2f(Px, Py);
    xp[25] = pack2f(Pz, g_lgr[p]);

    float* ob = out + (size_t)b * 64 * NN + n;
#pragma unroll 4
    for (int o = 0; o < 64; o++) {
        const unsigned long long* w = (const unsigned long long*)(sE + o * 52);
        unsigned long long acc = 0ull;
#pragma unroll
        for (int cp = 0; cp < 26; cp++) acc = ffma2(w[cp], xp[cp], acc);
        float2 u = unpack2(acc);
        float a = u.x + u.y + sE0[o];
        ob[(size_t)o * NN] = fmaxf(fmaf(a, sG4[o], sB4[o]), 0.f);
    }
}

// -------------------------------- launcher --------------------------------------
extern "C" void kernel_launch(void* const* d_in, const int* in_sizes, int n_in,
                              void* d_out, int out_size)
{
    const float* feature = (const float*)d_in[0];
    const float* xyz     = (const float*)d_in[1];
    const float* m1W  = (const float*)d_in[2];
    const float* m1g  = (const float*)d_in[3];
    const float* m1b  = (const float*)d_in[4];
    const float* lm1W = (const float*)d_in[5];
    const float* lm1g = (const float*)d_in[6];
    const float* lm1b = (const float*)d_in[7];
    const float* lm2W = (const float*)d_in[8];
    const float* lm2g = (const float*)d_in[9];
    const float* lm2b = (const float*)d_in[10];
    const float* p1fcW= (const float*)d_in[11];
    const float* p1mW = (const float*)d_in[12];
    const float* p1mg = (const float*)d_in[13];
    const float* p1mb = (const float*)d_in[14];
    const float* p2fcW= (const float*)d_in[15];
    const float* p2mW = (const float*)d_in[16];
    const float* p2mg = (const float*)d_in[17];
    const float* p2mb = (const float*)d_in[18];
    const float* m2W  = (const float*)d_in[19];
    const float* m2g  = (const float*)d_in[20];
    const float* m2b  = (const float*)d_in[21];
    const float* scW  = (const float*)d_in[22];
    const float* scg  = (const float*)d_in[23];
    const float* scb  = (const float*)d_in[24];
    const float* m3W  = (const float*)d_in[25];
    const float* m3g  = (const float*)d_in[26];
    const float* m3b  = (const float*)d_in[27];
    const float* m4W  = (const float*)d_in[28];
    const float* m4g  = (const float*)d_in[29];
    const float* m4b  = (const float*)d_in[30];
    const int*   nidx = (const int*)d_in[31];
    float* out = (float*)d_out;

    kSetup<<<7, 512>>>(m4W, m2W, m2g, m2b, scW, scg, scb, m3W, m3g, m3b, m4g, m4b);
    kA<<<(BN + 255) / 256, 256>>>(feature, m1W, m1g, m1b);
    kB<<<1184, 256>>>(xyz, nidx, lm1W, lm1g, lm1b, p1fcW, p1mW, p1mg, p1mb);
    kC<<<592, 256>>>(nidx, lm2W, lm2g, lm2b, p2fcW, p2mW, p2mg, p2mb);
    kD<<<BN / (8 * 32), 256>>>(feature, xyz, out);
}

// round 14
// speedup vs baseline: 1.5129x; 1.0738x over previous
#include <cuda_runtime.h>
#include <math.h>

#define BB 4
#define NN 20480
#define KK 16
#define BN (BB*NN)      // 81920 points
#define NPAIR (BN/2)
#define CAT_S 20        // padded cat row stride (floats)
#define CAT_BUF 688     // per-point cat buffer stride (floats): 688 % 32 == 16 -> halves disjoint banks

// ---------------- scratch ----------------
__device__ float g_feat0[BN*16];
__device__ float g_feat1[BN*16];
__device__ float g_lrep[(size_t)BN*256];   // [p][k][c]
__device__ float g_gdis[BN*16];            // [p][k]
__device__ float g_lgr[BN];                // [p]
__device__ float g_tmp2[(size_t)BN*32];    // p2m output, [p][32]
__device__ float g_Ecat[64*52];
__device__ float g_e0[64];
__device__ float g_g4[64];
__device__ float g_b4[64];

// ---------------- packed f32x2 helpers ----------------
__device__ __forceinline__ unsigned long long ffma2(unsigned long long a,
                                                    unsigned long long b,
                                                    unsigned long long c)
{
    unsigned long long d;
    asm("fma.rn.f32x2 %0, %1, %2, %3;" : "=l"(d) : "l"(a), "l"(b), "l"(c));
    return d;
}
__device__ __forceinline__ unsigned long long pack2(float x)
{
    unsigned long long d;
    asm("mov.b64 %0, {%1, %1};" : "=l"(d) : "f"(x));
    return d;
}
__device__ __forceinline__ unsigned long long pack2f(float lo, float hi)
{
    unsigned long long d;
    asm("mov.b64 %0, {%1, %2};" : "=l"(d) : "f"(lo), "f"(hi));
    return d;
}
__device__ __forceinline__ float2 unpack2(unsigned long long v)
{
    float lo, hi;
    asm("mov.b64 {%0, %1}, %2;" : "=f"(lo), "=f"(hi) : "l"(v));
    return make_float2(lo, hi);
}
__device__ __forceinline__ unsigned long long f2u(float2 v)
{
    unsigned long long r;
    memcpy(&r, &v, 8);
    return r;
}

// ---------------- Kernel Setup: fold linear tail ----------------
__global__ void kSetup(const float* __restrict__ m4W,
                       const float* __restrict__ m2W, const float* __restrict__ m2g, const float* __restrict__ m2b,
                       const float* __restrict__ scW, const float* __restrict__ scg, const float* __restrict__ scb,
                       const float* __restrict__ m3W, const float* __restrict__ m3g, const float* __restrict__ m3b,
                       const float* __restrict__ m4g, const float* __restrict__ m4b)
{
    int t = blockIdx.x * blockDim.x + threadIdx.x;
    if (t < 3328) {
        int o = t / 52, c = t % 52;
        float s = 0.f;
        if (c < 32) {
            for (int j = 0; j < 64; j++) s += m4W[o * 128 + j] * m2g[j] * m2W[j * 32 + c];
        } else if (c < 48) {
            int cc = c - 32;
            for (int j = 0; j < 64; j++) s += m4W[o * 128 + j] * scg[j] * scW[j * 16 + cc];
        } else {
            int cc = c - 48;
            for (int j = 0; j < 64; j++) s += m4W[o * 128 + 64 + j] * m3g[j] * m3W[j * 4 + cc];
        }
        g_Ecat[o * 52 + c] = s;
    } else if (t < 3392) {
        int o = t - 3328;
        float s = 0.f;
        for (int j = 0; j < 64; j++)
            s += m4W[o * 128 + j] * (m2b[j] + scb[j]) + m4W[o * 128 + 64 + j] * m3b[j];
        g_e0[o] = s;
        g_g4[o] = m4g[o];
        g_b4[o] = m4b[o];
    }
}

// ---------------- Kernel A ----------------
__global__ void __launch_bounds__(256) kA(const float* __restrict__ feature,
                                          const float* __restrict__ W,
                                          const float* __restrict__ g,
                                          const float* __restrict__ bia)
{
    __shared__ float sW[256], sg[16], sb[16];
    int tid = threadIdx.x;
    sW[tid] = W[tid];
    if (tid < 16) { sg[tid] = g[tid]; sb[tid] = bia[tid]; }
    __syncthreads();
    int p = blockIdx.x * 256 + tid;
    if (p >= BN) return;
    int b = p / NN, n = p - b * NN;
    const float* f = feature + (size_t)b * 16 * NN + n;
    float x[16];
#pragma unroll
    for (int c = 0; c < 16; c++) x[c] = f[(size_t)c * NN];
#pragma unroll
    for (int o = 0; o < 16; o++) {
        float a = 0.f;
#pragma unroll
        for (int c = 0; c < 16; c++) a = fmaf(sW[o * 16 + c], x[c], a);
        g_feat0[(size_t)p * 16 + o] = fmaxf(fmaf(a, sg[o], sb[o]), 0.f);
    }
}

// -------- attention pool (lane = output channel) ----------
__device__ __forceinline__ float pool_lane(const float* __restrict__ cat,
                                           const float* __restrict__ fcT, int c)
{
    unsigned long long acc[8];
#pragma unroll
    for (int t = 0; t < 8; t++) acc[t] = 0ull;
#pragma unroll
    for (int i = 0; i < 34; i++) {
        unsigned long long w2 = pack2(fcT[i * 33 + c]);
        const ulonglong2* row = (const ulonglong2*)(cat + i * CAT_S);
        ulonglong2 r0 = row[0], r1 = row[1], r2 = row[2], r3 = row[3];
        acc[0] = ffma2(w2, r0.x, acc[0]); acc[1] = ffma2(w2, r0.y, acc[1]);
        acc[2] = ffma2(w2, r1.x, acc[2]); acc[3] = ffma2(w2, r1.y, acc[3]);
        acc[4] = ffma2(w2, r2.x, acc[4]); acc[5] = ffma2(w2, r2.y, acc[5]);
        acc[6] = ffma2(w2, r3.x, acc[6]); acc[7] = ffma2(w2, r3.y, acc[7]);
    }
    float a[16];
#pragma unroll
    for (int t = 0; t < 8; t++) { float2 u = unpack2(acc[t]); a[2*t] = u.x; a[2*t+1] = u.y; }
    float m = a[0];
#pragma unroll
    for (int t = 1; t < 16; t++) m = fmaxf(m, a[t]);
    float s = 0.f;
#pragma unroll
    for (int t = 0; t < 16; t++) { a[t] = __expf(a[t] - m); s += a[t]; }
    const float4* fr = (const float4*)(cat + (2 + c) * CAT_S);
    float4 f0 = fr[0], f1 = fr[1], f2 = fr[2], f3 = fr[3];
    float fl = a[0] * f0.x + a[1] * f0.y + a[2]  * f0.z + a[3]  * f0.w
             + a[4] * f1.x + a[5] * f1.y + a[6]  * f1.z + a[7]  * f1.w
             + a[8] * f2.x + a[9] * f2.y + a[10] * f2.z + a[11] * f2.w
             + a[12]* f3.x + a[13]* f3.y + a[14] * f3.z + a[15] * f3.w;
    return fl / s;
}

// ---------------- Kernel B: 2 points per warp ----------------
#define WB 8
// shared float offsets (kB)
#define B_LW1P 0        /* 144: lm1 packed [i(9)][cp(8)][2] */
#define B_LG   144
#define B_LB   160
#define B_PG   176
#define B_PB   192
#define B_FC   208      /* 34*33 = 1122 */
#define B_PM   1330     /* 32*17 = 544 */
#define B_FLC  1874     /* 8 warps * 2 * 36 = 576 (8B aligned: 1874 even) */
#define B_CAT  2452     /* 16B aligned; 8 warps * 2 * 688 = 11008 */
#define B_SMEMF (B_CAT + WB * 2 * CAT_BUF)   /* 13460 floats = 53840 B */

__global__ void __launch_bounds__(256, 3) kB(
    const float* __restrict__ xyz, const int* __restrict__ nidx,
    const float* __restrict__ lm1W, const float* __restrict__ lm1g, const float* __restrict__ lm1b,
    const float* __restrict__ fcW,
    const float* __restrict__ pmW, const float* __restrict__ pmg, const float* __restrict__ pmb)
{
    extern __shared__ float sh[];
    int tid = threadIdx.x;
    for (int t = tid; t < 144; t += 256) {
        int i = t >> 4, r = t & 15, cp = r >> 1, e = r & 1;
        sh[B_LW1P + t] = lm1W[(2 * cp + e) * 9 + i];
    }
    if (tid < 16) { sh[B_LG + tid] = lm1g[tid]; sh[B_LB + tid] = lm1b[tid];
                    sh[B_PG + tid] = pmg[tid];  sh[B_PB + tid] = pmb[tid]; }
    for (int t = tid; t < 1088; t += 256) { int o = t / 34, i = t - o * 34; sh[B_FC + i * 33 + o] = fcW[t]; }
    for (int t = tid; t < 512;  t += 256) { int o = t >> 5, c = t & 31;     sh[B_PM + c * 17 + o] = pmW[t]; }
    __syncthreads();

    int warp = tid >> 5, lane = tid & 31, kk = lane & 15, h = lane >> 4, cbase = h * 8;
    float* cat2 = sh + B_CAT + warp * 2 * CAT_BUF;
    float* flc2 = sh + B_FLC + warp * 72;            // [2][36]
    const float2* w1p = (const float2*)(sh + B_LW1P);
    int nwarps = gridDim.x * WB;
    for (int pr = blockIdx.x * WB + warp; pr < NPAIR; pr += nwarps) {
        int base = pr * 2, b = base / NN;
        int p = base + h;                             // this lane's point
        float* catH = cat2 + h * CAT_BUF;
        // ---- geometry (per-lane point; no half duplication) ----
        float Px = xyz[(size_t)p * 3 + 0], Py = xyz[(size_t)p * 3 + 1], Pz = xyz[(size_t)p * 3 + 2];
        int idx = nidx[(size_t)p * 16 + kk];
        int nbp = b * NN + idx;
        float Qx = xyz[(size_t)nbp * 3 + 0], Qy = xyz[(size_t)nbp * 3 + 1], Qz = xyz[(size_t)nbp * 3 + 2];
        float rx = Px - Qx, ry = Py - Qy, rz = Pz - Qz;
        float rxy2 = rx * rx + ry * ry;
        float rd = sqrtf(rxy2 + rz * rz);
        float ral = atan2f(ry, rx);
        float rbe = atan2f(rz, sqrtf(rxy2));
        float gd = __expf(-rd);
        float maxd = rd, sx = Qx, sy = Qy, sz = Qz;
#pragma unroll
        for (int off = 8; off; off >>= 1) {
            maxd = fmaxf(maxd, __shfl_xor_sync(0xffffffffu, maxd, off));
            sx += __shfl_xor_sync(0xffffffffu, sx, off);
            sy += __shfl_xor_sync(0xffffffffu, sy, off);
            sz += __shfl_xor_sync(0xffffffffu, sz, off);
        }
        float dvx = Px - sx * (1.f / 16.f), dvy = Py - sy * (1.f / 16.f), dvz = Pz - sz * (1.f / 16.f);
        float dal = atan2f(dvy, dvx);
        float dbe = atan2f(dvz, sqrtf(dvx * dvx + dvy * dvy));
        float rep[9] = { ral - dal, rbe - dbe, rd, Px, Py, Pz, Qx, Qy, Qz };
        // ---- lm1: all 16 channels, f32x2 channel pairs, uniform smem weights ----
        unsigned long long racc[8];
#pragma unroll
        for (int cp = 0; cp < 8; cp++) racc[cp] = 0ull;
#pragma unroll
        for (int i = 0; i < 9; i++) {
            unsigned long long r2 = pack2(rep[i]);
#pragma unroll
            for (int cp = 0; cp < 8; cp++)
                racc[cp] = ffma2(f2u(w1p[i * 8 + cp]), r2, racc[cp]);
        }
        float lrv[16];
#pragma unroll
        for (int cp = 0; cp < 8; cp++) {
            float2 u = unpack2(racc[cp]);
            float2 gg = ((const float2*)(sh + B_LG))[cp];
            float2 bb = ((const float2*)(sh + B_LB))[cp];
            lrv[2 * cp]     = fmaxf(fmaf(u.x, gg.x, bb.x), 0.f);
            lrv[2 * cp + 1] = fmaxf(fmaf(u.y, gg.y, bb.y), 0.f);
        }
#pragma unroll
        for (int c = 0; c < 16; c++) catH[(18 + c) * CAT_S + kk] = lrv[c];
        {
            float4* dst = (float4*)(g_lrep + (size_t)p * 256 + kk * 16);
            dst[0] = make_float4(lrv[0], lrv[1], lrv[2], lrv[3]);
            dst[1] = make_float4(lrv[4], lrv[5], lrv[6], lrv[7]);
            dst[2] = make_float4(lrv[8], lrv[9], lrv[10], lrv[11]);
            dst[3] = make_float4(lrv[12], lrv[13], lrv[14], lrv[15]);
        }
        catH[kk] = gd;
        g_gdis[(size_t)p * 16 + kk] = gd;
        if (kk == 0) {
            float gn2 = Px * Px + Py * Py + Pz * Pz;
            g_lgr[p] = (maxd * maxd * maxd) / (gn2 * sqrtf(gn2));
        }
        __syncwarp();
        // ---- phases: gather + f_dis + f_set + pool, per point ----
#pragma unroll 1
        for (int ph = 0; ph < 2; ph++) {
            int P = base + ph;
            float* catP = cat2 + ph * CAT_BUF;
            int idxP = nidx[(size_t)P * 16 + kk];
            int nbpP = b * NN + idxP;
            const float4* fq = (const float4*)(g_feat0 + (size_t)nbpP * 16 + cbase);
            float4 a0 = fq[0], a1 = fq[1];
            const float4* fp4 = (const float4*)(g_feat0 + (size_t)P * 16 + cbase);
            float4 c0 = fp4[0], c1 = fp4[1];
            float pa = fabsf(a0.x - c0.x) + fabsf(a0.y - c0.y) + fabsf(a0.z - c0.z) + fabsf(a0.w - c0.w)
                     + fabsf(a1.x - c1.x) + fabsf(a1.y - c1.y) + fabsf(a1.z - c1.z) + fabsf(a1.w - c1.w);
            pa += __shfl_xor_sync(0xffffffffu, pa, 16);
            if (h == 0) catP[CAT_S + kk] = __expf(-pa * (1.f / 16.f)) * 2.0f;
            float av[8] = { a0.x, a0.y, a0.z, a0.w, a1.x, a1.y, a1.z, a1.w };
#pragma unroll
            for (int j = 0; j < 8; j++) {
                int j2 = (j + 4) & 7;
                float v = h ? av[j2] : av[j];
                int row = 2 + cbase + (h ? j2 : j);
                catP[row * CAT_S + kk] = v;
            }
            __syncwarp();
            float fl = pool_lane(catP, sh + B_FC, lane);
            flc2[ph * 36 + lane] = fl;
            __syncwarp();
        }
        // ---- p1m: o = kk, point = base + h (full warp) ----
        {
            float a = 0.f;
            const float* fl = flc2 + h * 36;
#pragma unroll
            for (int c = 0; c < 32; c++) a = fmaf(sh[B_PM + c * 17 + kk], fl[c], a);
            g_feat1[(size_t)p * 16 + kk] = fmaxf(fmaf(a, sh[B_PG + kk], sh[B_PB + kk]), 0.f);
        }
        __syncwarp();
    }
}

// ---------------- Kernel C: 2 points per warp ----------------
#define WC 8
#define C_W2P  0        /* 256: lm2 packed [i(16)][cp(8)][2] */
#define C_LG   256
#define C_LB   272
#define C_PG   288
#define C_PB   320
#define C_FC   352      /* 1122 */
#define C_P2   1474     /* 1024: p2m packed [cp][o][2] (8B aligned: 1474 even) */
#define C_FLC  2498     /* 576 */
#define C_CAT  3076     /* 16B aligned; 11008 */
#define C_SMEMF (C_CAT + WC * 2 * CAT_BUF)   /* 14084 floats = 56336 B */

__global__ void __launch_bounds__(256, 3) kC(
    const int* __restrict__ nidx,
    const float* __restrict__ lm2W, const float* __restrict__ lm2g, const float* __restrict__ lm2b,
    const float* __restrict__ fc2W,
    const float* __restrict__ p2mW, const float* __restrict__ p2mg, const float* __restrict__ p2mb)
{
    extern __shared__ float sh[];
    int tid = threadIdx.x;
    for (int t = tid; t < 256; t += 256) {
        int i = t >> 4, r = t & 15, cp = r >> 1, e = r & 1;
        sh[C_W2P + t] = lm2W[(2 * cp + e) * 16 + i];
    }
    if (tid < 16) { sh[C_LG + tid] = lm2g[tid]; sh[C_LB + tid] = lm2b[tid]; }
    if (tid < 32) { sh[C_PG + tid] = p2mg[tid]; sh[C_PB + tid] = p2mb[tid]; }
    for (int t = tid; t < 1088; t += 256) { int o = t / 34, i = t - o * 34; sh[C_FC + i * 33 + o] = fc2W[t]; }
    for (int t = tid; t < 1024; t += 256) {
        int cp = t >> 6, o = (t >> 1) & 31, e = t & 1;
        sh[C_P2 + t] = p2mW[o * 32 + cp * 2 + e];
    }
    __syncthreads();

    int warp = tid >> 5, lane = tid & 31, kk = lane & 15, h = lane >> 4, cbase = h * 8;
    float* cat2 = sh + C_CAT + warp * 2 * CAT_BUF;
    float* flc2 = sh + C_FLC + warp * 72;
    const float2* w2p = (const float2*)(sh + C_W2P);
    const unsigned long long* wp2m = (const unsigned long long*)(sh + C_P2);
    int nwarps = gridDim.x * WC;
    for (int pr = blockIdx.x * WC + warp; pr < NPAIR; pr += nwarps) {
        int base = pr * 2, b = base / NN;
        int p = base + h;
        float* catH = cat2 + h * CAT_BUF;
        // ---- lrep2: all 16 channels, f32x2 channel pairs, uniform smem weights ----
        float lr[16];
        {
            const float4* lq = (const float4*)(g_lrep + (size_t)p * 256 + kk * 16);
            float4 L0 = lq[0], L1 = lq[1], L2 = lq[2], L3 = lq[3];
            lr[0]=L0.x; lr[1]=L0.y; lr[2]=L0.z; lr[3]=L0.w;
            lr[4]=L1.x; lr[5]=L1.y; lr[6]=L1.z; lr[7]=L1.w;
            lr[8]=L2.x; lr[9]=L2.y; lr[10]=L2.z; lr[11]=L2.w;
            lr[12]=L3.x; lr[13]=L3.y; lr[14]=L3.z; lr[15]=L3.w;
        }
        unsigned long long lacc[8];
#pragma unroll
        for (int cp = 0; cp < 8; cp++) lacc[cp] = 0ull;
#pragma unroll
        for (int i = 0; i < 16; i++) {
            unsigned long long r2 = pack2(lr[i]);
#pragma unroll
            for (int cp = 0; cp < 8; cp++)
                lacc[cp] = ffma2(f2u(w2p[i * 8 + cp]), r2, lacc[cp]);
        }
#pragma unroll
        for (int cp = 0; cp < 8; cp++) {
            float2 u = unpack2(lacc[cp]);
            float2 gg = ((const float2*)(sh + C_LG))[cp];
            float2 bb = ((const float2*)(sh + C_LB))[cp];
            catH[(18 + 2 * cp) * CAT_S + kk]     = fmaxf(fmaf(u.x, gg.x, bb.x), 0.f);
            catH[(18 + 2 * cp + 1) * CAT_S + kk] = fmaxf(fmaf(u.y, gg.y, bb.y), 0.f);
        }
        catH[kk] = g_gdis[(size_t)p * 16 + kk];
        __syncwarp();
        // ---- phases ----
#pragma unroll 1
        for (int ph = 0; ph < 2; ph++) {
            int P = base + ph;
            float* catP = cat2 + ph * CAT_BUF;
            int idxP = nidx[(size_t)P * 16 + kk];
            int nbpP = b * NN + idxP;
            const float4* fq = (const float4*)(g_feat1 + (size_t)nbpP * 16 + cbase);
            float4 a0 = fq[0], a1 = fq[1];
            const float4* fp4 = (const float4*)(g_feat1 + (size_t)P * 16 + cbase);
            float4 c0 = fp4[0], c1 = fp4[1];
            float pa = fabsf(a0.x - c0.x) + fabsf(a0.y - c0.y) + fabsf(a0.z - c0.z) + fabsf(a0.w - c0.w)
                     + fabsf(a1.x - c1.x) + fabsf(a1.y - c1.y) + fabsf(a1.z - c1.z) + fabsf(a1.w - c1.w);
            pa += __shfl_xor_sync(0xffffffffu, pa, 16);
            if (h == 0) catP[CAT_S + kk] = __expf(-pa * (1.f / 16.f)) * 2.0f;
            float av[8] = { a0.x, a0.y, a0.z, a0.w, a1.x, a1.y, a1.z, a1.w };
#pragma unroll
            for (int j = 0; j < 8; j++) {
                int j2 = (j + 4) & 7;
                float v = h ? av[j2] : av[j];
                int row = 2 + cbase + (h ? j2 : j);
                catP[row * CAT_S + kk] = v;
            }
            __syncwarp();
            float fl = pool_lane(catP, sh + C_FC, lane);
            flc2[ph * 36 + lane] = fl;
            __syncwarp();
        }
        // ---- p2m for both points (sequential, full warp o = lane) ----
#pragma unroll 1
        for (int ph = 0; ph < 2; ph++) {
            const unsigned long long* f2 = (const unsigned long long*)(flc2 + ph * 36);
            unsigned long long acc2 = 0ull;
#pragma unroll
            for (int cp = 0; cp < 16; cp++) acc2 = ffma2(wp2m[cp * 32 + lane], f2[cp], acc2);
            float2 u = unpack2(acc2);
            float a = u.x + u.y;
            g_tmp2[(size_t)(base + ph) * 32 + lane] =
                fmaxf(fmaf(a, sh[C_PG + lane], sh[C_PB + lane]), 0.f);
        }
        __syncwarp();
    }
}

// ---------------- Kernel D: folded tail, lane = point ----------------
__global__ void __launch_bounds__(256) kD(const float* __restrict__ feature,
                                          const float* __restrict__ xyz,
                                          float* __restrict__ out)
{
    __shared__ __align__(8) float sE[64 * 52];
    __shared__ float sE0[64], sG4[64], sB4[64];
    int tid = threadIdx.x;
    for (int t = tid; t < 64 * 52; t += 256) sE[t] = g_Ecat[t];
    if (tid < 64) { sE0[tid] = g_e0[tid]; sG4[tid] = g_g4[tid]; sB4[tid] = g_b4[tid]; }
    __syncthreads();

    int warp = tid >> 5, lane = tid & 31;
    int p = (blockIdx.x * 8 + warp) * 32 + lane;   // grid(320)*8*32 == BN
    int b = p / NN, n = p - b * NN;

    unsigned long long xp[26];
    const ulonglong2* tq = (const ulonglong2*)(g_tmp2 + (size_t)p * 32);
#pragma unroll
    for (int q = 0; q < 8; q++) { ulonglong2 v = tq[q]; xp[2 * q] = v.x; xp[2 * q + 1] = v.y; }
    const float* fb = feature + (size_t)b * 16 * NN + n;
#pragma unroll
    for (int cp = 0; cp < 8; cp++)
        xp[16 + cp] = pack2f(fb[(size_t)(2 * cp) * NN], fb[(size_t)(2 * cp + 1) * NN]);
    float Px = xyz[(size_t)p * 3], Py = xyz[(size_t)p * 3 + 1], Pz = xyz[(size_t)p * 3 + 2];
    xp[24] = pack2f(Px, Py);
    xp[25] = pack2f(Pz, g_lgr[p]);

    float* ob = out + (size_t)b * 64 * NN + n;
#pragma unroll 4
    for (int o = 0; o < 64; o++) {
        const unsigned long long* w = (const unsigned long long*)(sE + o * 52);
        unsigned long long acc = 0ull;
#pragma unroll
        for (int cp = 0; cp < 26; cp++) acc = ffma2(w[cp], xp[cp], acc);
        float2 u = unpack2(acc);
        float a = u.x + u.y + sE0[o];
        ob[(size_t)o * NN] = fmaxf(fmaf(a, sG4[o], sB4[o]), 0.f);
    }
}

// -------------------------------- launcher --------------------------------------
extern "C" void kernel_launch(void* const* d_in, const int* in_sizes, int n_in,
                              void* d_out, int out_size)
{
    const float* feature = (const float*)d_in[0];
    const float* xyz     = (const float*)d_in[1];
    const float* m1W  = (const float*)d_in[2];
    const float* m1g  = (const float*)d_in[3];
    const float* m1b  = (const float*)d_in[4];
    const float* lm1W = (const float*)d_in[5];
    const float* lm1g = (const float*)d_in[6];
    const float* lm1b = (const float*)d_in[7];
    const float* lm2W = (const float*)d_in[8];
    const float* lm2g = (const float*)d_in[9];
    const float* lm2b = (const float*)d_in[10];
    const float* p1fcW= (const float*)d_in[11];
    const float* p1mW = (const float*)d_in[12];
    const float* p1mg = (const float*)d_in[13];
    const float* p1mb = (const float*)d_in[14];
    const float* p2fcW= (const float*)d_in[15];
    const float* p2mW = (const float*)d_in[16];
    const float* p2mg = (const float*)d_in[17];
    const float* p2mb = (const float*)d_in[18];
    const float* m2W  = (const float*)d_in[19];
    const float* m2g  = (const float*)d_in[20];
    const float* m2b  = (const float*)d_in[21];
    const float* scW  = (const float*)d_in[22];
    const float* scg  = (const float*)d_in[23];
    const float* scb  = (const float*)d_in[24];
    const float* m3W  = (const float*)d_in[25];
    const float* m3g  = (const float*)d_in[26];
    const float* m3b  = (const float*)d_in[27];
    const float* m4W  = (const float*)d_in[28];
    const float* m4g  = (const float*)d_in[29];
    const float* m4b  = (const float*)d_in[30];
    const int*   nidx = (const int*)d_in[31];
    float* out = (float*)d_out;

    static bool attr_done = false;
    if (!attr_done) {
        cudaFuncSetAttribute(kB, cudaFuncAttributeMaxDynamicSharedMemorySize,
                             B_SMEMF * (int)sizeof(float));
        cudaFuncSetAttribute(kC, cudaFuncAttributeMaxDynamicSharedMemorySize,
                             C_SMEMF * (int)sizeof(float));
        attr_done = true;
    }

    kSetup<<<7, 512>>>(m4W, m2W, m2g, m2b, scW, scg, scb, m3W, m3g, m3b, m4g, m4b);
    kA<<<(BN + 255) / 256, 256>>>(feature, m1W, m1g, m1b);
    kB<<<444, 256, B_SMEMF * sizeof(float)>>>(xyz, nidx, lm1W, lm1g, lm1b, p1fcW, p1mW, p1mg, p1mb);
    kC<<<444, 256, C_SMEMF * sizeof(float)>>>(nidx, lm2W, lm2g, lm2b, p2fcW, p2mW, p2mg, p2mb);
    kD<<<BN / (8 * 32), 256>>>(feature, xyz, out);
}